// round 5
// baseline (speedup 1.0000x reference)
#include <cuda_runtime.h>
#include <math.h>

#define BB 4
#define NN 4096
#define MM 4096
#define CCH 64
#define KK 32
#define RADIUS 0.1f
#define RAD2 0.01f
#define EPSV 1e-5f

// ---------------- device scratch ----------------
__device__ int      g_idx[BB * NN * KK];
__device__ unsigned g_nbr[BB * NN];
__device__ int      g_idxnn[BB * NN];
__device__ float    g_Wgeff[CCH * CCH];       // Wg2@Wg1  row-major [o][i]
__device__ float    g_Wqi[CCH * CCH];         // Wgeff@Wphi
__device__ float    g_Wqj[CCH * CCH];         // Wgeff@Wpsi
__device__ float    g_bconst[CCH];            // Wgeff@(bphi-bpsi) + Wg2@bg1 + bg2
__device__ float    g_Qi[BB * MM * CCH];      // per-support precomputed
__device__ float    g_Qj[BB * MM * CCH];
__device__ float    g_AF[BB * MM * CCH];

// ---------------- kernel 1: warp-bitonic top-K ----------------
__device__ __forceinline__ void bsort32(float& d, int& ix, int lane) {
#pragma unroll
    for (int k = 2; k <= 32; k <<= 1) {
#pragma unroll
        for (int j = k >> 1; j > 0; j >>= 1) {
            float od = __shfl_xor_sync(0xffffffffu, d, j);
            int   oi = __shfl_xor_sync(0xffffffffu, ix, j);
            bool keepMin = (((lane & k) == 0) == ((lane & j) == 0));
            bool take = keepMin ? (od < d) : (od > d);
            if (take) { d = od; ix = oi; }
        }
    }
}
__device__ __forceinline__ void bmerge32(float& d, int& ix, int lane) {
#pragma unroll
    for (int j = 16; j > 0; j >>= 1) {
        float od = __shfl_xor_sync(0xffffffffu, d, j);
        int   oi = __shfl_xor_sync(0xffffffffu, ix, j);
        bool keepMin = ((lane & j) == 0);
        bool take = keepMin ? (od < d) : (od > d);
        if (take) { d = od; ix = oi; }
    }
}

__global__ __launch_bounds__(256) void k_knn(const float* __restrict__ qxyz,
                                             const float* __restrict__ sxyz,
                                             const int* __restrict__ smask) {
    __shared__ float sx[MM], sy[MM], sz[MM];
    int b   = blockIdx.x >> 9;
    int grp = blockIdx.x & 511;
    for (int i = threadIdx.x; i < MM; i += 256) {
        bool v = smask[b * MM + i] > 0;
        float x = sxyz[(b * MM + i) * 3 + 0];
        float y = sxyz[(b * MM + i) * 3 + 1];
        float z = sxyz[(b * MM + i) * 3 + 2];
        sx[i] = v ? x : 1e18f;
        sy[i] = v ? y : 1e18f;
        sz[i] = v ? z : 1e18f;
    }
    __syncthreads();

    int warp = threadIdx.x >> 5, lane = threadIdx.x & 31;
    int n  = grp * 8 + warp;
    int qi = b * NN + n;
    float qx = qxyz[qi * 3 + 0];
    float qy = qxyz[qi * 3 + 1];
    float qz = qxyz[qi * 3 + 2];

    float bd = INFINITY; int bi = 0;
    float thr = INFINITY;
    for (int ch = 0; ch < MM / 32; ++ch) {
        int m = ch * 32 + lane;
        float dx = qx - sx[m], dy = qy - sy[m], dz = qz - sz[m];
        float d2 = fmaf(dx, dx, fmaf(dy, dy, dz * dz));
        if (__ballot_sync(0xffffffffu, d2 < thr)) {
            float nd = d2; int ni = m;
            bsort32(nd, ni, lane);
            float rd = __shfl_sync(0xffffffffu, nd, 31 ^ lane);
            int   ri = __shfl_sync(0xffffffffu, ni, 31 ^ lane);
            if (rd < bd) { bd = rd; bi = ri; }
            bmerge32(bd, bi, lane);
            thr = __shfl_sync(0xffffffffu, bd, 31);
        }
    }
    g_idx[qi * KK + lane] = bi;
    unsigned nb = __ballot_sync(0xffffffffu, bd <= RAD2);
    if (lane == 0) { g_nbr[qi] = nb; g_idxnn[qi] = bi; }
}

// ---------------- kernel 2: compose weight matrices ----------------
__global__ __launch_bounds__(256) void k_compose(
    const float* __restrict__ Wg1, const float* __restrict__ Wg2,
    const float* __restrict__ Wphi, const float* __restrict__ Wpsi,
    const float* __restrict__ bphi, const float* __restrict__ bpsi,
    const float* __restrict__ bg1, const float* __restrict__ bg2) {
    __shared__ float G[CCH * CCH];
    int tid = threadIdx.x;
    for (int e = tid; e < 4096; e += 256) {
        int o = e >> 6, i = e & 63;
        float a = 0.f;
        for (int c = 0; c < 64; ++c)
            a = fmaf(Wg2[o * 64 + c], Wg1[c * 64 + i], a);
        G[e] = a;
        g_Wgeff[e] = a;
    }
    __syncthreads();
    for (int e = tid; e < 4096; e += 256) {
        int o = e >> 6, i = e & 63;
        float qi = 0.f, qj = 0.f;
        for (int c = 0; c < 64; ++c) {
            float g = G[o * 64 + c];
            qi = fmaf(g, Wphi[c * 64 + i], qi);
            qj = fmaf(g, Wpsi[c * 64 + i], qj);
        }
        g_Wqi[e] = qi;
        g_Wqj[e] = qj;
    }
    if (tid < 64) {
        float a = bg2[tid];
        for (int c = 0; c < 64; ++c)
            a = fmaf(Wg2[tid * 64 + c], bg1[c], a);
        for (int i = 0; i < 64; ++i)
            a = fmaf(G[tid * 64 + i], bphi[i] - bpsi[i], a);
        g_bconst[tid] = a;
    }
}

// ---------------- kernel 3: per-support precompute (reads feat directly) ----------------
#define STRD 36
constexpr int PRE_WQI = 0, PRE_WQJ = 4096, PRE_WAL = 8192, PRE_X = 12288;
constexpr int PRE_SM = PRE_X + 64 * STRD;   // 14592 floats = 58368 B

__global__ __launch_bounds__(256) void k_pre(const float* __restrict__ feat,
                                             const float* __restrict__ Wal) {
    extern __shared__ float s[];
    int tid = threadIdx.x;
    for (int e = tid; e < 4096; e += 256) {
        int o = e >> 6, in = e & 63;
        s[PRE_WQI + in * 64 + o] = g_Wqi[e];
        s[PRE_WQJ + in * 64 + o] = g_Wqj[e];
        s[PRE_WAL + in * 64 + o] = Wal[e];
    }

    int base = blockIdx.x * 32;                 // global point id over B*M
    int b    = base >> 12;
    int m0   = base & (MM - 1);
    int c = tid & 63, g = tid >> 6, k0 = g * 8;
    float* xS = s + PRE_X;
    for (int i = tid; i < 2048; i += 256) {
        int k = i & 31, cc = i >> 5;
        xS[cc * STRD + k] = feat[((long)b * CCH + cc) * MM + m0 + k];
    }
    __syncthreads();

    float qi[8], qj[8], af[8];
#pragma unroll
    for (int kk = 0; kk < 8; ++kk) { qi[kk] = 0.f; qj[kk] = 0.f; af[kk] = 0.f; }
    const float* Wi = s + PRE_WQI + c;
    const float* Wj = s + PRE_WQJ + c;
    const float* Wa = s + PRE_WAL + c;
    const float* xb = xS + k0;
#pragma unroll 4
    for (int c2 = 0; c2 < 64; ++c2) {
        float wi = Wi[c2 * 64], wj = Wj[c2 * 64], wa = Wa[c2 * 64];
        float4 x0 = *(const float4*)(xb + c2 * STRD);
        float4 x1 = *(const float4*)(xb + c2 * STRD + 4);
        qi[0] = fmaf(wi, x0.x, qi[0]); qi[1] = fmaf(wi, x0.y, qi[1]);
        qi[2] = fmaf(wi, x0.z, qi[2]); qi[3] = fmaf(wi, x0.w, qi[3]);
        qi[4] = fmaf(wi, x1.x, qi[4]); qi[5] = fmaf(wi, x1.y, qi[5]);
        qi[6] = fmaf(wi, x1.z, qi[6]); qi[7] = fmaf(wi, x1.w, qi[7]);
        qj[0] = fmaf(wj, x0.x, qj[0]); qj[1] = fmaf(wj, x0.y, qj[1]);
        qj[2] = fmaf(wj, x0.z, qj[2]); qj[3] = fmaf(wj, x0.w, qj[3]);
        qj[4] = fmaf(wj, x1.x, qj[4]); qj[5] = fmaf(wj, x1.y, qj[5]);
        qj[6] = fmaf(wj, x1.z, qj[6]); qj[7] = fmaf(wj, x1.w, qj[7]);
        af[0] = fmaf(wa, x0.x, af[0]); af[1] = fmaf(wa, x0.y, af[1]);
        af[2] = fmaf(wa, x0.z, af[2]); af[3] = fmaf(wa, x0.w, af[3]);
        af[4] = fmaf(wa, x1.x, af[4]); af[5] = fmaf(wa, x1.y, af[5]);
        af[6] = fmaf(wa, x1.z, af[6]); af[7] = fmaf(wa, x1.w, af[7]);
    }
#pragma unroll
    for (int kk = 0; kk < 8; ++kk) {
        long o = (long)(base + k0 + kk) * 64 + c;
        g_Qi[o] = qi[kk];
        g_Qj[o] = qj[kk];
        g_AF[o] = af[kk];
    }
}

// ---------------- kernel 4: fused per-query kernel (thread-local softmax) ----------------
struct P2 {
    const float *qxyz, *sxyz;
    const int   *qmask;
    const float *Wth1, *bth1, *Wth2, *bth2;
    const float *bal;
    const float *gt, *bet, *rmt, *rvt, *gg, *beg, *rmg, *rvg;
    float* out;
};

constexpr int OFF_WG   = 0;       // WgT[c2][c] 4096
constexpr int OFF_WEFF = 4096;    // 64*4 theta-fold
constexpr int OFF_CC   = 4352;    // bal(64) | bconst(64)
constexpr int OFF_BN   = 4480;    // 4*64
constexpr int OFF_Q    = 4736;
// per-query: dl [64*36] | pos [32*4] | fm [32] | kidx [32]
constexpr int QO_DL = 0, QO_POS = 2304, QO_FM = 2432, QO_KIDX = 2464;
constexpr int QSZ = 2496;
constexpr int SMEM_FLOATS = OFF_Q + 4 * QSZ;   // 14720 floats = 58880 B

__global__ __launch_bounds__(512, 2) void k_main(P2 p) {
    extern __shared__ float sm[];
    int tid = threadIdx.x;

    // ---- init ----
    {
        for (int i = tid; i < 4096; i += 512) {
            int o = i >> 6, in = i & 63;
            sm[OFF_WG + in * 64 + o] = g_Wgeff[i];
        }
        if (tid < 192) {
            int cc = tid / 3, j = tid - 3 * cc;
            float acc = 0.f;
            for (int c2 = 0; c2 < 64; ++c2)
                acc = fmaf(p.Wth2[cc * 64 + c2], p.Wth1[c2 * 3 + j], acc);
            sm[OFF_WEFF + cc * 4 + j] = acc;
        } else if (tid < 256) {
            int cc = tid - 192;
            float acc = p.bth2[cc];
            for (int c2 = 0; c2 < 64; ++c2)
                acc = fmaf(p.Wth2[cc * 64 + c2], p.bth1[c2], acc);
            sm[OFF_WEFF + cc * 4 + 3] = acc;
        } else if (tid < 320) {
            int i = tid - 256;
            sm[OFF_CC + i]      = p.bal[i];
            sm[OFF_CC + 64 + i] = g_bconst[i];
            float it = p.gt[i] * rsqrtf(p.rvt[i] + EPSV);
            sm[OFF_BN + 0 * 64 + i] = it;
            sm[OFF_BN + 1 * 64 + i] = p.bet[i] - p.rmt[i] * it;
            float ig = p.gg[i] * rsqrtf(p.rvg[i] + EPSV);
            sm[OFF_BN + 2 * 64 + i] = ig;
            sm[OFF_BN + 3 * 64 + i] = p.beg[i] - p.rmg[i] * ig;
        }
    }
    __syncthreads();

    int lq = tid >> 7;          // local query 0..3
    int t  = tid & 127;
    int c  = t >> 1;            // channel
    int h  = t & 1;             // k-half
    int kb = h * 16;

    float* Q    = sm + OFF_Q + lq * QSZ;
    float* dlB  = Q + QO_DL;
    float* posB = Q + QO_POS;
    float* fmB  = Q + QO_FM;
    int*   kidx = (int*)(Q + QO_KIDX);

    float b_al  = sm[OFF_CC + c];
    float bcn   = sm[OFF_CC + 64 + c];
    float inv_t = sm[OFF_BN + 0 * 64 + c];
    float sh_t  = sm[OFF_BN + 1 * 64 + c];
    float inv_g = sm[OFF_BN + 2 * 64 + c];
    float sh_g  = sm[OFF_BN + 3 * 64 + c];
    float we0   = sm[OFF_WEFF + c * 4 + 0];
    float we1   = sm[OFF_WEFF + c * 4 + 1];
    float we2   = sm[OFF_WEFF + c * 4 + 2];
    float beff  = sm[OFF_WEFF + c * 4 + 3];

    const int ngrp = (BB * NN) / 4;
    for (int grp = blockIdx.x; grp < ngrp; grp += gridDim.x) {
        int qi = grp * 4 + lq;
        int b  = qi >> 12;
        int n  = qi & (NN - 1);
        long rowbase = (long)b * MM;

        // ---- setup: first 32 threads of each query group ----
        if (t < 32) {
            int k  = t;
            int ki = g_idx[qi * KK + k];
            kidx[k] = ki;
            float qx = p.qxyz[qi * 3 + 0];
            float qy = p.qxyz[qi * 3 + 1];
            float qz = p.qxyz[qi * 3 + 2];
            const float* s = p.sxyz + (rowbase + ki) * 3;
            float4 pp;
            pp.x = (s[0] - qx) * (1.0f / RADIUS);
            pp.y = (s[1] - qy) * (1.0f / RADIUS);
            pp.z = (s[2] - qz) * (1.0f / RADIUS);
            pp.w = 0.f;
            *(float4*)(posB + k * 4) = pp;
            unsigned nb = g_nbr[qi];
            int qm = p.qmask[qi];
            fmB[k] = (float)((nb >> k) & 1u) + (1.0f - (float)qm);
        }
        __syncthreads();   // S1

        // ---- phase B: delta row for own channel, k in [kb, kb+16) ----
        {
            float4 dv[4];
#pragma unroll
            for (int kk = 0; kk < 16; ++kk) {
                float4 pp = *(const float4*)(posB + (kb + kk) * 4);
                float dpre = beff;
                dpre = fmaf(we0, pp.x, dpre);
                dpre = fmaf(we1, pp.y, dpre);
                dpre = fmaf(we2, pp.z, dpre);
                (&dv[kk >> 2].x)[kk & 3] = fmaxf(fmaf(dpre, inv_t, sh_t), 0.f);
            }
#pragma unroll
            for (int i = 0; i < 4; ++i)
                *(float4*)(dlB + c * STRD + kb + i * 4) = dv[i];
        }
        float qic = g_Qi[(rowbase + g_idxnn[qi]) * 64 + c];
        __syncthreads();   // S2

        // ---- matvec: acc[k] = (Wgeff @ delta)[c][kb..kb+15] ----
        float acc[16];
#pragma unroll
        for (int kk = 0; kk < 16; ++kk) acc[kk] = 0.f;
        {
            const float* W  = sm + OFF_WG + c;
            const float* db = dlB + kb;
#pragma unroll 4
            for (int c2 = 0; c2 < 64; ++c2) {
                float w = W[c2 * 64];
                float4 d0 = *(const float4*)(db + c2 * STRD);
                float4 d1 = *(const float4*)(db + c2 * STRD + 4);
                float4 d2 = *(const float4*)(db + c2 * STRD + 8);
                float4 d3 = *(const float4*)(db + c2 * STRD + 12);
                acc[0]  = fmaf(w, d0.x, acc[0]);  acc[1]  = fmaf(w, d0.y, acc[1]);
                acc[2]  = fmaf(w, d0.z, acc[2]);  acc[3]  = fmaf(w, d0.w, acc[3]);
                acc[4]  = fmaf(w, d1.x, acc[4]);  acc[5]  = fmaf(w, d1.y, acc[5]);
                acc[6]  = fmaf(w, d1.z, acc[6]);  acc[7]  = fmaf(w, d1.w, acc[7]);
                acc[8]  = fmaf(w, d2.x, acc[8]);  acc[9]  = fmaf(w, d2.y, acc[9]);
                acc[10] = fmaf(w, d2.z, acc[10]); acc[11] = fmaf(w, d2.w, acc[11]);
                acc[12] = fmaf(w, d3.x, acc[12]); acc[13] = fmaf(w, d3.y, acc[13]);
                acc[14] = fmaf(w, d3.z, acc[14]); acc[15] = fmaf(w, d3.w, acc[15]);
            }
        }

        // ---- epilogue: rel2 (in place), local+pair softmax, weighted sum ----
#pragma unroll
        for (int kk = 0; kk < 16; ++kk) {
            float qjv = g_Qj[(rowbase + kidx[kb + kk]) * 64 + c];
            float pre2 = qic - qjv + acc[kk] + bcn;
            acc[kk] = fmaxf(fmaf(pre2, inv_g, sh_g), 0.f);
        }
        float mx = acc[0];
#pragma unroll
        for (int kk = 1; kk < 16; ++kk) mx = fmaxf(mx, acc[kk]);
        mx = fmaxf(mx, __shfl_xor_sync(0xffffffffu, mx, 1));

        float se = 0.f, sf = 0.f;
        {
            const float* dr = dlB + c * STRD + kb;
#pragma unroll
            for (int kk = 0; kk < 16; ++kk) {
                float e  = __expf(acc[kk] - mx);
                float af = g_AF[(rowbase + kidx[kb + kk]) * 64 + c];
                float ftv = (af + b_al + dr[kk]) * fmB[kb + kk];
                se += e;
                sf = fmaf(e, ftv, sf);
            }
        }
        se += __shfl_xor_sync(0xffffffffu, se, 1);
        sf += __shfl_xor_sync(0xffffffffu, sf, 1);
        if (h == 0)
            p.out[((long)b * CCH + c) * NN + n] = sf / se;
        __syncthreads();   // S3
    }
}

// ---------------- host launcher ----------------
extern "C" void kernel_launch(void* const* d_in, const int* in_sizes, int n_in,
                              void* d_out, int out_size) {
    const float* qxyz  = (const float*)d_in[0];
    const float* sxyz  = (const float*)d_in[1];
    const int*   qmask = (const int*)d_in[2];
    const int*   smask = (const int*)d_in[3];
    const float* feat  = (const float*)d_in[4];
    const float* Wth1  = (const float*)d_in[5];
    const float* bth1  = (const float*)d_in[6];
    const float* Wth2  = (const float*)d_in[7];
    const float* bth2  = (const float*)d_in[8];
    const float* Wphi  = (const float*)d_in[9];
    const float* bphi  = (const float*)d_in[10];
    const float* Wpsi  = (const float*)d_in[11];
    const float* bpsi  = (const float*)d_in[12];
    const float* Wal   = (const float*)d_in[13];
    const float* bal   = (const float*)d_in[14];
    const float* Wg1   = (const float*)d_in[15];
    const float* bg1   = (const float*)d_in[16];
    const float* Wg2   = (const float*)d_in[17];
    const float* bg2   = (const float*)d_in[18];

    P2 p;
    p.qxyz = qxyz; p.sxyz = sxyz; p.qmask = qmask;
    p.Wth1 = Wth1; p.bth1 = bth1; p.Wth2 = Wth2; p.bth2 = bth2;
    p.bal  = bal;
    p.gt   = (const float*)d_in[19]; p.bet  = (const float*)d_in[20];
    p.rmt  = (const float*)d_in[21]; p.rvt  = (const float*)d_in[22];
    p.gg   = (const float*)d_in[23]; p.beg  = (const float*)d_in[24];
    p.rmg  = (const float*)d_in[25]; p.rvg  = (const float*)d_in[26];
    p.out  = (float*)d_out;

    k_compose<<<1, 256>>>(Wg1, Wg2, Wphi, Wpsi, bphi, bpsi, bg1, bg2);
    k_knn<<<(BB * NN) / 8, 256>>>(qxyz, sxyz, smask);

    cudaFuncSetAttribute(k_pre, cudaFuncAttributeMaxDynamicSharedMemorySize,
                         PRE_SM * 4);
    k_pre<<<(BB * MM) / 32, 256, PRE_SM * 4>>>(feat, Wal);

    cudaFuncSetAttribute(k_main, cudaFuncAttributeMaxDynamicSharedMemorySize,
                         SMEM_FLOATS * 4);
    int dev = 0, nsm = 148;
    cudaGetDevice(&dev);
    cudaDeviceGetAttribute(&nsm, cudaDevAttrMultiProcessorCount, dev);
    k_main<<<2 * nsm, 512, SMEM_FLOATS * 4>>>(p);
}

// round 6
// speedup vs baseline: 1.6050x; 1.6050x over previous
#include <cuda_runtime.h>
#include <math.h>

#define BB 4
#define NN 4096
#define MM 4096
#define CCH 64
#define KK 32
#define RADIUS 0.1f
#define RAD2 0.01f
#define EPSV 1e-5f

// ---------------- device scratch ----------------
__device__ int      g_idx[BB * NN * KK];
__device__ unsigned g_nbr[BB * NN];
__device__ int      g_idxnn[BB * NN];
__device__ float    g_Wgeff[CCH * CCH];
__device__ float    g_Wqi[CCH * CCH];
__device__ float    g_Wqj[CCH * CCH];
__device__ float    g_bconst[CCH];
__device__ float    g_Qi[BB * MM * CCH];
__device__ float    g_Qj[BB * MM * CCH];
__device__ float    g_AF[BB * MM * CCH];

// ---------------- warp-bitonic helpers ----------------
__device__ __forceinline__ void bsort32(float& d, int& ix, int lane) {
#pragma unroll
    for (int k = 2; k <= 32; k <<= 1) {
#pragma unroll
        for (int j = k >> 1; j > 0; j >>= 1) {
            float od = __shfl_xor_sync(0xffffffffu, d, j);
            int   oi = __shfl_xor_sync(0xffffffffu, ix, j);
            bool keepMin = (((lane & k) == 0) == ((lane & j) == 0));
            bool take = keepMin ? (od < d) : (od > d);
            if (take) { d = od; ix = oi; }
        }
    }
}
__device__ __forceinline__ void bmerge32(float& d, int& ix, int lane) {
#pragma unroll
    for (int j = 16; j > 0; j >>= 1) {
        float od = __shfl_xor_sync(0xffffffffu, d, j);
        int   oi = __shfl_xor_sync(0xffffffffu, ix, j);
        bool keepMin = ((lane & j) == 0);
        bool take = keepMin ? (od < d) : (od > d);
        if (take) { d = od; ix = oi; }
    }
}

// ---------------- kernel 1: top-K with candidate buffering ----------------
// dyn smem: sx[4096] sy[4096] sz[4096] bufD[8][64] bufI[8][64]
constexpr int KNN_SM_FLOATS = 3 * MM + 8 * 64 * 2;   // 13312 floats = 53248 B

__global__ __launch_bounds__(256) void k_knn(const float* __restrict__ qxyz,
                                             const float* __restrict__ sxyz,
                                             const int* __restrict__ smask) {
    extern __shared__ float dsm[];
    float* sx = dsm;
    float* sy = dsm + MM;
    float* sz = dsm + 2 * MM;
    int b   = blockIdx.x >> 9;
    int grp = blockIdx.x & 511;
    for (int i = threadIdx.x; i < MM; i += 256) {
        bool v = smask[b * MM + i] > 0;
        float x = sxyz[(b * MM + i) * 3 + 0];
        float y = sxyz[(b * MM + i) * 3 + 1];
        float z = sxyz[(b * MM + i) * 3 + 2];
        sx[i] = v ? x : 1e18f;
        sy[i] = v ? y : 1e18f;
        sz[i] = v ? z : 1e18f;
    }
    __syncthreads();

    int warp = threadIdx.x >> 5, lane = threadIdx.x & 31;
    float* bD = dsm + 3 * MM + warp * 64;
    int*   bI = (int*)(dsm + 3 * MM + 512) + warp * 64;

    int n  = grp * 8 + warp;
    int qi = b * NN + n;
    float qx = qxyz[qi * 3 + 0];
    float qy = qxyz[qi * 3 + 1];
    float qz = qxyz[qi * 3 + 2];

    float bd = INFINITY; int bi = 0;
    float thr = INFINITY;
    int cnt = 0;
    for (int ch = 0; ch < MM / 32; ++ch) {
        int m = ch * 32 + lane;
        float dx = qx - sx[m], dy = qy - sy[m], dz = qz - sz[m];
        float d2 = fmaf(dx, dx, fmaf(dy, dy, dz * dz));
        bool pass = d2 < thr;
        unsigned mask = __ballot_sync(0xffffffffu, pass);
        if (mask) {
            int pos = cnt + __popc(mask & ((1u << lane) - 1u));
            if (pass) { bD[pos] = d2; bI[pos] = m; }
            cnt += __popc(mask);
            if (cnt >= 32) {
                __syncwarp();
                float nd = bD[lane]; int ni = bI[lane];
                bsort32(nd, ni, lane);
                float rd = __shfl_sync(0xffffffffu, nd, 31 ^ lane);
                int   ri = __shfl_sync(0xffffffffu, ni, 31 ^ lane);
                if (rd < bd) { bd = rd; bi = ri; }
                bmerge32(bd, bi, lane);
                thr = __shfl_sync(0xffffffffu, bd, 31);
                cnt -= 32;
                float sd = 0.f; int si = 0;
                if (lane < cnt) { sd = bD[32 + lane]; si = bI[32 + lane]; }
                __syncwarp();
                if (lane < cnt) { bD[lane] = sd; bI[lane] = si; }
                __syncwarp();
            }
        }
    }
    if (cnt > 0) {            // tail (cnt <= 31)
        __syncwarp();
        float nd = (lane < cnt) ? bD[lane] : INFINITY;
        int   ni = (lane < cnt) ? bI[lane] : 0;
        bsort32(nd, ni, lane);
        float rd = __shfl_sync(0xffffffffu, nd, 31 ^ lane);
        int   ri = __shfl_sync(0xffffffffu, ni, 31 ^ lane);
        if (rd < bd) { bd = rd; bi = ri; }
        bmerge32(bd, bi, lane);
    }
    g_idx[qi * KK + lane] = bi;
    unsigned nb = __ballot_sync(0xffffffffu, bd <= RAD2);
    if (lane == 0) { g_nbr[qi] = nb; g_idxnn[qi] = bi; }
}

// ---------------- kernel 2: compose weight matrices ----------------
__global__ __launch_bounds__(256) void k_compose(
    const float* __restrict__ Wg1, const float* __restrict__ Wg2,
    const float* __restrict__ Wphi, const float* __restrict__ Wpsi,
    const float* __restrict__ bphi, const float* __restrict__ bpsi,
    const float* __restrict__ bg1, const float* __restrict__ bg2) {
    __shared__ float G[CCH * CCH];
    int tid = threadIdx.x;
    for (int e = tid; e < 4096; e += 256) {
        int o = e >> 6, i = e & 63;
        float a = 0.f;
        for (int c = 0; c < 64; ++c)
            a = fmaf(Wg2[o * 64 + c], Wg1[c * 64 + i], a);
        G[e] = a;
        g_Wgeff[e] = a;
    }
    __syncthreads();
    for (int e = tid; e < 4096; e += 256) {
        int o = e >> 6, i = e & 63;
        float qi = 0.f, qj = 0.f;
        for (int c = 0; c < 64; ++c) {
            float g = G[o * 64 + c];
            qi = fmaf(g, Wphi[c * 64 + i], qi);
            qj = fmaf(g, Wpsi[c * 64 + i], qj);
        }
        g_Wqi[e] = qi;
        g_Wqj[e] = qj;
    }
    if (tid < 64) {
        float a = bg2[tid];
        for (int c = 0; c < 64; ++c)
            a = fmaf(Wg2[tid * 64 + c], bg1[c], a);
        for (int i = 0; i < 64; ++i)
            a = fmaf(G[tid * 64 + i], bphi[i] - bpsi[i], a);
        g_bconst[tid] = a;
    }
}

// ---------------- kernel 3: per-support precompute ----------------
#define STRD 36
constexpr int PRE_WQI = 0, PRE_WQJ = 4096, PRE_WAL = 8192, PRE_X = 12288;
constexpr int PRE_SM = PRE_X + 64 * STRD;   // 14592 floats

__global__ __launch_bounds__(256) void k_pre(const float* __restrict__ feat,
                                             const float* __restrict__ Wal) {
    extern __shared__ float s[];
    int tid = threadIdx.x;
    for (int e = tid; e < 4096; e += 256) {
        int o = e >> 6, in = e & 63;
        s[PRE_WQI + in * 64 + o] = g_Wqi[e];
        s[PRE_WQJ + in * 64 + o] = g_Wqj[e];
        s[PRE_WAL + in * 64 + o] = Wal[e];
    }

    int base = blockIdx.x * 32;
    int b    = base >> 12;
    int m0   = base & (MM - 1);
    int c = tid & 63, g = tid >> 6, k0 = g * 8;
    float* xS = s + PRE_X;
    for (int i = tid; i < 2048; i += 256) {
        int k = i & 31, cc = i >> 5;
        xS[cc * STRD + k] = feat[((long)b * CCH + cc) * MM + m0 + k];
    }
    __syncthreads();

    float qi[8], qj[8], af[8];
#pragma unroll
    for (int kk = 0; kk < 8; ++kk) { qi[kk] = 0.f; qj[kk] = 0.f; af[kk] = 0.f; }
    const float* Wi = s + PRE_WQI + c;
    const float* Wj = s + PRE_WQJ + c;
    const float* Wa = s + PRE_WAL + c;
    const float* xb = xS + k0;
#pragma unroll 4
    for (int c2 = 0; c2 < 64; ++c2) {
        float wi = Wi[c2 * 64], wj = Wj[c2 * 64], wa = Wa[c2 * 64];
        float4 x0 = *(const float4*)(xb + c2 * STRD);
        float4 x1 = *(const float4*)(xb + c2 * STRD + 4);
        qi[0] = fmaf(wi, x0.x, qi[0]); qi[1] = fmaf(wi, x0.y, qi[1]);
        qi[2] = fmaf(wi, x0.z, qi[2]); qi[3] = fmaf(wi, x0.w, qi[3]);
        qi[4] = fmaf(wi, x1.x, qi[4]); qi[5] = fmaf(wi, x1.y, qi[5]);
        qi[6] = fmaf(wi, x1.z, qi[6]); qi[7] = fmaf(wi, x1.w, qi[7]);
        qj[0] = fmaf(wj, x0.x, qj[0]); qj[1] = fmaf(wj, x0.y, qj[1]);
        qj[2] = fmaf(wj, x0.z, qj[2]); qj[3] = fmaf(wj, x0.w, qj[3]);
        qj[4] = fmaf(wj, x1.x, qj[4]); qj[5] = fmaf(wj, x1.y, qj[5]);
        qj[6] = fmaf(wj, x1.z, qj[6]); qj[7] = fmaf(wj, x1.w, qj[7]);
        af[0] = fmaf(wa, x0.x, af[0]); af[1] = fmaf(wa, x0.y, af[1]);
        af[2] = fmaf(wa, x0.z, af[2]); af[3] = fmaf(wa, x0.w, af[3]);
        af[4] = fmaf(wa, x1.x, af[4]); af[5] = fmaf(wa, x1.y, af[5]);
        af[6] = fmaf(wa, x1.z, af[6]); af[7] = fmaf(wa, x1.w, af[7]);
    }
#pragma unroll
    for (int kk = 0; kk < 8; ++kk) {
        long o = (long)(base + k0 + kk) * 64 + c;
        g_Qi[o] = qi[kk];
        g_Qj[o] = qj[kk];
        g_AF[o] = af[kk];
    }
}

// ---------------- kernel 4: fused per-query kernel (R4 structure) ----------------
struct P2 {
    const float *qxyz, *sxyz;
    const int   *qmask;
    const float *Wth1, *bth1, *Wth2, *bth2;
    const float *bal;
    const float *gt, *bet, *rmt, *rvt, *gg, *beg, *rmg, *rvg;
    float* out;
};

constexpr int OFF_WG   = 0;       // WgT[c2][c] 4096
constexpr int OFF_WEFF = 4096;    // 64*4 theta-fold
constexpr int OFF_CC   = 4352;    // bal(64) | bconst(64)
constexpr int OFF_BN   = 4480;    // 4*64
constexpr int OFF_Q    = 4736;
constexpr int QO_QJ = 0, QO_AF = 2304, QO_DL = 4608;
constexpr int QO_POS = 6912, QO_FM = 7008, QO_QI = 7040, QO_RED = 7104, QO_KIDX = 7872;
constexpr int QSZ = 7904;
constexpr int SMEM_FLOATS = OFF_Q + 2 * QSZ;   // 20544 floats = 82176 B

__global__ __launch_bounds__(512, 2) void k_main(P2 p) {
    extern __shared__ float sm[];
    int tid = threadIdx.x;

    {
        for (int i = tid; i < 4096; i += 512) {
            int o = i >> 6, in = i & 63;
            sm[OFF_WG + in * 64 + o] = g_Wgeff[i];
        }
        if (tid < 192) {
            int cc = tid / 3, j = tid - 3 * cc;
            float acc = 0.f;
            for (int c2 = 0; c2 < 64; ++c2)
                acc = fmaf(p.Wth2[cc * 64 + c2], p.Wth1[c2 * 3 + j], acc);
            sm[OFF_WEFF + cc * 4 + j] = acc;
        } else if (tid < 256) {
            int cc = tid - 192;
            float acc = p.bth2[cc];
            for (int c2 = 0; c2 < 64; ++c2)
                acc = fmaf(p.Wth2[cc * 64 + c2], p.bth1[c2], acc);
            sm[OFF_WEFF + cc * 4 + 3] = acc;
        } else if (tid < 320) {
            int i = tid - 256;
            sm[OFF_CC + i]      = p.bal[i];
            sm[OFF_CC + 64 + i] = g_bconst[i];
            float it = p.gt[i] * rsqrtf(p.rvt[i] + EPSV);
            sm[OFF_BN + 0 * 64 + i] = it;
            sm[OFF_BN + 1 * 64 + i] = p.bet[i] - p.rmt[i] * it;
            float ig = p.gg[i] * rsqrtf(p.rvg[i] + EPSV);
            sm[OFF_BN + 2 * 64 + i] = ig;
            sm[OFF_BN + 3 * 64 + i] = p.beg[i] - p.rmg[i] * ig;
        }
    }
    __syncthreads();

    int q  = tid >> 8;
    int t  = tid & 255;
    int c  = t & 63;
    int g  = t >> 6;
    int k0 = g * 8;

    float* Q    = sm + OFF_Q + q * QSZ;
    float* QjB  = Q + QO_QJ;
    float* AFB  = Q + QO_AF;
    float* dlB  = Q + QO_DL;
    float* posB = Q + QO_POS;
    float* fmB  = Q + QO_FM;
    float* qiB  = Q + QO_QI;
    float* red  = Q + QO_RED;
    int*   kidx = (int*)(Q + QO_KIDX);

    float b_al  = sm[OFF_CC + c];
    float bcn   = sm[OFF_CC + 64 + c];
    float inv_t = sm[OFF_BN + 0 * 64 + c];
    float sh_t  = sm[OFF_BN + 1 * 64 + c];
    float inv_g = sm[OFF_BN + 2 * 64 + c];
    float sh_g  = sm[OFF_BN + 3 * 64 + c];
    float we0   = sm[OFF_WEFF + c * 4 + 0];
    float we1   = sm[OFF_WEFF + c * 4 + 1];
    float we2   = sm[OFF_WEFF + c * 4 + 2];
    float beff  = sm[OFF_WEFF + c * 4 + 3];

    const int npairs = (BB * NN) / 2;
    for (int pair = blockIdx.x; pair < npairs; pair += gridDim.x) {
        int qi = pair * 2 + q;
        int b  = qi >> 12;
        int n  = qi & (NN - 1);

        if (t < 32) {
            int k  = t;
            int ki = g_idx[qi * KK + k];
            kidx[k] = ki;
            float qx = p.qxyz[qi * 3 + 0];
            float qy = p.qxyz[qi * 3 + 1];
            float qz = p.qxyz[qi * 3 + 2];
            const float* s = p.sxyz + ((long)b * MM + ki) * 3;
            posB[0 * 32 + k] = (s[0] - qx) * (1.0f / RADIUS);
            posB[1 * 32 + k] = (s[1] - qy) * (1.0f / RADIUS);
            posB[2 * 32 + k] = (s[2] - qz) * (1.0f / RADIUS);
            unsigned nb = g_nbr[qi];
            int qm = p.qmask[qi];
            fmB[k] = (float)((nb >> k) & 1u) + (1.0f - (float)qm);
        } else if (t < 96) {
            int cc = t - 32;
            qiB[cc] = g_Qi[((long)b * MM + g_idxnn[qi]) * 64 + cc];
        }
        __syncthreads();   // S1

        for (int i = t; i < 2048; i += 256) {
            int cc = i & 63, k = i >> 6;
            long o = ((long)b * MM + kidx[k]) * 64 + cc;
            QjB[cc * STRD + k] = g_Qj[o];
            AFB[cc * STRD + k] = g_AF[o];
        }
        float dl[8];
        {
            float4 d0, d1;
#pragma unroll
            for (int kk = 0; kk < 8; ++kk) {
                int k = k0 + kk;
                float dpre = beff;
                dpre = fmaf(we0, posB[0 * 32 + k], dpre);
                dpre = fmaf(we1, posB[1 * 32 + k], dpre);
                dpre = fmaf(we2, posB[2 * 32 + k], dpre);
                dl[kk] = fmaxf(fmaf(dpre, inv_t, sh_t), 0.f);
                if (kk < 4) (&d0.x)[kk] = dl[kk]; else (&d1.x)[kk - 4] = dl[kk];
            }
            *(float4*)(dlB + c * STRD + k0) = d0;
            *(float4*)(dlB + c * STRD + k0 + 4) = d1;
        }
        __syncthreads();   // S2

        float acc[8];
#pragma unroll
        for (int kk = 0; kk < 8; ++kk) acc[kk] = 0.f;
        {
            const float* W  = sm + OFF_WG + c;
            const float* db = dlB + k0;
#pragma unroll 4
            for (int c2 = 0; c2 < 64; ++c2) {
                float w = W[c2 * 64];
                float4 d0 = *(const float4*)(db + c2 * STRD);
                float4 d1 = *(const float4*)(db + c2 * STRD + 4);
                acc[0] = fmaf(w, d0.x, acc[0]); acc[1] = fmaf(w, d0.y, acc[1]);
                acc[2] = fmaf(w, d0.z, acc[2]); acc[3] = fmaf(w, d0.w, acc[3]);
                acc[4] = fmaf(w, d1.x, acc[4]); acc[5] = fmaf(w, d1.y, acc[5]);
                acc[6] = fmaf(w, d1.z, acc[6]); acc[7] = fmaf(w, d1.w, acc[7]);
            }
        }

        float qic = qiB[c];
        float4 qj0 = *(const float4*)(QjB + c * STRD + k0);
        float4 qj1 = *(const float4*)(QjB + c * STRD + k0 + 4);
        float4 af0 = *(const float4*)(AFB + c * STRD + k0);
        float4 af1 = *(const float4*)(AFB + c * STRD + k0 + 4);
        float v[8], ft[8];
#pragma unroll
        for (int kk = 0; kk < 8; ++kk) {
            float qjv = (kk < 4) ? (&qj0.x)[kk] : (&qj1.x)[kk - 4];
            float afv = (kk < 4) ? (&af0.x)[kk] : (&af1.x)[kk - 4];
            float pre2 = qic - qjv + acc[kk] + bcn;
            v[kk] = fmaxf(fmaf(pre2, inv_g, sh_g), 0.f);
            ft[kk] = (afv + b_al + dl[kk]) * fmB[k0 + kk];
        }
        float mx = v[0];
#pragma unroll
        for (int kk = 1; kk < 8; ++kk) mx = fmaxf(mx, v[kk]);
        red[g * 64 + c] = mx;
        __syncthreads();   // S3
        float M = fmaxf(fmaxf(red[c], red[64 + c]), fmaxf(red[128 + c], red[192 + c]));
        float se = 0.f, sf = 0.f;
#pragma unroll
        for (int kk = 0; kk < 8; ++kk) {
            float e = __expf(v[kk] - M);
            se += e;
            sf = fmaf(e, ft[kk], sf);
        }
        red[256 + g * 64 + c] = se;
        red[512 + g * 64 + c] = sf;
        __syncthreads();   // S4
        if (g == 0) {
            float SE = red[256 + c] + red[320 + c] + red[384 + c] + red[448 + c];
            float SF = red[512 + c] + red[576 + c] + red[640 + c] + red[704 + c];
            p.out[((long)b * CCH + c) * NN + n] = SF / SE;
        }
        __syncthreads();   // S5
    }
}

// ---------------- host launcher ----------------
extern "C" void kernel_launch(void* const* d_in, const int* in_sizes, int n_in,
                              void* d_out, int out_size) {
    const float* qxyz  = (const float*)d_in[0];
    const float* sxyz  = (const float*)d_in[1];
    const int*   qmask = (const int*)d_in[2];
    const int*   smask = (const int*)d_in[3];
    const float* feat  = (const float*)d_in[4];
    const float* Wth1  = (const float*)d_in[5];
    const float* bth1  = (const float*)d_in[6];
    const float* Wth2  = (const float*)d_in[7];
    const float* bth2  = (const float*)d_in[8];
    const float* Wphi  = (const float*)d_in[9];
    const float* bphi  = (const float*)d_in[10];
    const float* Wpsi  = (const float*)d_in[11];
    const float* bpsi  = (const float*)d_in[12];
    const float* Wal   = (const float*)d_in[13];
    const float* bal   = (const float*)d_in[14];
    const float* Wg1   = (const float*)d_in[15];
    const float* bg1   = (const float*)d_in[16];
    const float* Wg2   = (const float*)d_in[17];
    const float* bg2   = (const float*)d_in[18];

    P2 p;
    p.qxyz = qxyz; p.sxyz = sxyz; p.qmask = qmask;
    p.Wth1 = Wth1; p.bth1 = bth1; p.Wth2 = Wth2; p.bth2 = bth2;
    p.bal  = bal;
    p.gt   = (const float*)d_in[19]; p.bet  = (const float*)d_in[20];
    p.rmt  = (const float*)d_in[21]; p.rvt  = (const float*)d_in[22];
    p.gg   = (const float*)d_in[23]; p.beg  = (const float*)d_in[24];
    p.rmg  = (const float*)d_in[25]; p.rvg  = (const float*)d_in[26];
    p.out  = (float*)d_out;

    k_compose<<<1, 256>>>(Wg1, Wg2, Wphi, Wpsi, bphi, bpsi, bg1, bg2);

    cudaFuncSetAttribute(k_knn, cudaFuncAttributeMaxDynamicSharedMemorySize,
                         KNN_SM_FLOATS * 4);
    k_knn<<<(BB * NN) / 8, 256, KNN_SM_FLOATS * 4>>>(qxyz, sxyz, smask);

    cudaFuncSetAttribute(k_pre, cudaFuncAttributeMaxDynamicSharedMemorySize,
                         PRE_SM * 4);
    k_pre<<<(BB * MM) / 32, 256, PRE_SM * 4>>>(feat, Wal);

    cudaFuncSetAttribute(k_main, cudaFuncAttributeMaxDynamicSharedMemorySize,
                         SMEM_FLOATS * 4);
    int dev = 0, nsm = 148;
    cudaGetDevice(&dev);
    cudaDeviceGetAttribute(&nsm, cudaDevAttrMultiProcessorCount, dev);
    k_main<<<2 * nsm, 512, SMEM_FLOATS * 4>>>(p);
}

// round 7
// speedup vs baseline: 2.6210x; 1.6330x over previous
#include <cuda_runtime.h>
#include <math.h>

#define BB 4
#define NN 4096
#define MM 4096
#define CCH 64
#define KK 32
#define RADIUS 0.1f
#define RAD2 0.01f
#define EPSV 1e-5f

// ---------------- device scratch ----------------
__device__ int      g_idx[BB * NN * KK];
__device__ unsigned g_nbr[BB * NN];
__device__ int      g_idxnn[BB * NN];
__device__ float    g_Wgeff[CCH * CCH];
__device__ float    g_Wqi[CCH * CCH];
__device__ float    g_Wqj[CCH * CCH];
__device__ float    g_bconst[CCH];
__device__ float    g_Qi[BB * MM * CCH];
__device__ float    g_Qj[BB * MM * CCH];
__device__ float    g_AF[BB * MM * CCH];

// ---------------- warp-bitonic helpers ----------------
__device__ __forceinline__ void bsort32(float& d, int& ix, int lane) {
#pragma unroll
    for (int k = 2; k <= 32; k <<= 1) {
#pragma unroll
        for (int j = k >> 1; j > 0; j >>= 1) {
            float od = __shfl_xor_sync(0xffffffffu, d, j);
            int   oi = __shfl_xor_sync(0xffffffffu, ix, j);
            bool keepMin = (((lane & k) == 0) == ((lane & j) == 0));
            bool take = keepMin ? (od < d) : (od > d);
            if (take) { d = od; ix = oi; }
        }
    }
}
__device__ __forceinline__ void bmerge32(float& d, int& ix, int lane) {
#pragma unroll
    for (int j = 16; j > 0; j >>= 1) {
        float od = __shfl_xor_sync(0xffffffffu, d, j);
        int   oi = __shfl_xor_sync(0xffffffffu, ix, j);
        bool keepMin = ((lane & j) == 0);
        bool take = keepMin ? (od < d) : (od > d);
        if (take) { d = od; ix = oi; }
    }
}

// ---------------- kernel 1: top-K with candidate buffering ----------------
constexpr int KNN_SM_FLOATS = 3 * MM + 8 * 64 * 2;

__global__ __launch_bounds__(256) void k_knn(const float* __restrict__ qxyz,
                                             const float* __restrict__ sxyz,
                                             const int* __restrict__ smask) {
    extern __shared__ float dsm[];
    float* sx = dsm;
    float* sy = dsm + MM;
    float* sz = dsm + 2 * MM;
    int b   = blockIdx.x >> 9;
    int grp = blockIdx.x & 511;
    for (int i = threadIdx.x; i < MM; i += 256) {
        bool v = smask[b * MM + i] > 0;
        float x = sxyz[(b * MM + i) * 3 + 0];
        float y = sxyz[(b * MM + i) * 3 + 1];
        float z = sxyz[(b * MM + i) * 3 + 2];
        sx[i] = v ? x : 1e18f;
        sy[i] = v ? y : 1e18f;
        sz[i] = v ? z : 1e18f;
    }
    __syncthreads();

    int warp = threadIdx.x >> 5, lane = threadIdx.x & 31;
    float* bD = dsm + 3 * MM + warp * 64;
    int*   bI = (int*)(dsm + 3 * MM + 512) + warp * 64;

    int n  = grp * 8 + warp;
    int qi = b * NN + n;
    float qx = qxyz[qi * 3 + 0];
    float qy = qxyz[qi * 3 + 1];
    float qz = qxyz[qi * 3 + 2];

    float bd = INFINITY; int bi = 0;
    float thr = INFINITY;
    int cnt = 0;
    for (int ch = 0; ch < MM / 32; ++ch) {
        int m = ch * 32 + lane;
        float dx = qx - sx[m], dy = qy - sy[m], dz = qz - sz[m];
        float d2 = fmaf(dx, dx, fmaf(dy, dy, dz * dz));
        bool pass = d2 < thr;
        unsigned mask = __ballot_sync(0xffffffffu, pass);
        if (mask) {
            int pos = cnt + __popc(mask & ((1u << lane) - 1u));
            if (pass) { bD[pos] = d2; bI[pos] = m; }
            cnt += __popc(mask);
            if (cnt >= 32) {
                __syncwarp();
                float nd = bD[lane]; int ni = bI[lane];
                bsort32(nd, ni, lane);
                float rd = __shfl_sync(0xffffffffu, nd, 31 ^ lane);
                int   ri = __shfl_sync(0xffffffffu, ni, 31 ^ lane);
                if (rd < bd) { bd = rd; bi = ri; }
                bmerge32(bd, bi, lane);
                thr = __shfl_sync(0xffffffffu, bd, 31);
                cnt -= 32;
                float sd = 0.f; int si = 0;
                if (lane < cnt) { sd = bD[32 + lane]; si = bI[32 + lane]; }
                __syncwarp();
                if (lane < cnt) { bD[lane] = sd; bI[lane] = si; }
                __syncwarp();
            }
        }
    }
    if (cnt > 0) {
        __syncwarp();
        float nd = (lane < cnt) ? bD[lane] : INFINITY;
        int   ni = (lane < cnt) ? bI[lane] : 0;
        bsort32(nd, ni, lane);
        float rd = __shfl_sync(0xffffffffu, nd, 31 ^ lane);
        int   ri = __shfl_sync(0xffffffffu, ni, 31 ^ lane);
        if (rd < bd) { bd = rd; bi = ri; }
        bmerge32(bd, bi, lane);
    }
    g_idx[qi * KK + lane] = bi;
    unsigned nb = __ballot_sync(0xffffffffu, bd <= RAD2);
    if (lane == 0) { g_nbr[qi] = nb; g_idxnn[qi] = bi; }
}

// ---------------- kernel 2: compose weight matrices ----------------
__global__ __launch_bounds__(256) void k_compose(
    const float* __restrict__ Wg1, const float* __restrict__ Wg2,
    const float* __restrict__ Wphi, const float* __restrict__ Wpsi,
    const float* __restrict__ bphi, const float* __restrict__ bpsi,
    const float* __restrict__ bg1, const float* __restrict__ bg2) {
    __shared__ float G[CCH * CCH];
    int tid = threadIdx.x;
    for (int e = tid; e < 4096; e += 256) {
        int o = e >> 6, i = e & 63;
        float a = 0.f;
        for (int c = 0; c < 64; ++c)
            a = fmaf(Wg2[o * 64 + c], Wg1[c * 64 + i], a);
        G[e] = a;
        g_Wgeff[e] = a;
    }
    __syncthreads();
    for (int e = tid; e < 4096; e += 256) {
        int o = e >> 6, i = e & 63;
        float qi = 0.f, qj = 0.f;
        for (int c = 0; c < 64; ++c) {
            float g = G[o * 64 + c];
            qi = fmaf(g, Wphi[c * 64 + i], qi);
            qj = fmaf(g, Wpsi[c * 64 + i], qj);
        }
        g_Wqi[e] = qi;
        g_Wqj[e] = qj;
    }
    if (tid < 64) {
        float a = bg2[tid];
        for (int c = 0; c < 64; ++c)
            a = fmaf(Wg2[tid * 64 + c], bg1[c], a);
        for (int i = 0; i < 64; ++i)
            a = fmaf(G[tid * 64 + i], bphi[i] - bpsi[i], a);
        g_bconst[tid] = a;
    }
}

// ---------------- kernel 3: per-support precompute ----------------
#define STRD 36
constexpr int PRE_WQI = 0, PRE_WQJ = 4096, PRE_WAL = 8192, PRE_X = 12288;
constexpr int PRE_SM = PRE_X + 64 * STRD;

__global__ __launch_bounds__(256) void k_pre(const float* __restrict__ feat,
                                             const float* __restrict__ Wal) {
    extern __shared__ float s[];
    int tid = threadIdx.x;
    for (int e = tid; e < 4096; e += 256) {
        int o = e >> 6, in = e & 63;
        s[PRE_WQI + in * 64 + o] = g_Wqi[e];
        s[PRE_WQJ + in * 64 + o] = g_Wqj[e];
        s[PRE_WAL + in * 64 + o] = Wal[e];
    }

    int base = blockIdx.x * 32;
    int b    = base >> 12;
    int m0   = base & (MM - 1);
    int c = tid & 63, g = tid >> 6, k0 = g * 8;
    float* xS = s + PRE_X;
    for (int i = tid; i < 2048; i += 256) {
        int k = i & 31, cc = i >> 5;
        xS[cc * STRD + k] = feat[((long)b * CCH + cc) * MM + m0 + k];
    }
    __syncthreads();

    float qi[8], qj[8], af[8];
#pragma unroll
    for (int kk = 0; kk < 8; ++kk) { qi[kk] = 0.f; qj[kk] = 0.f; af[kk] = 0.f; }
    const float* Wi = s + PRE_WQI + c;
    const float* Wj = s + PRE_WQJ + c;
    const float* Wa = s + PRE_WAL + c;
    const float* xb = xS + k0;
#pragma unroll 4
    for (int c2 = 0; c2 < 64; ++c2) {
        float wi = Wi[c2 * 64], wj = Wj[c2 * 64], wa = Wa[c2 * 64];
        float4 x0 = *(const float4*)(xb + c2 * STRD);
        float4 x1 = *(const float4*)(xb + c2 * STRD + 4);
        qi[0] = fmaf(wi, x0.x, qi[0]); qi[1] = fmaf(wi, x0.y, qi[1]);
        qi[2] = fmaf(wi, x0.z, qi[2]); qi[3] = fmaf(wi, x0.w, qi[3]);
        qi[4] = fmaf(wi, x1.x, qi[4]); qi[5] = fmaf(wi, x1.y, qi[5]);
        qi[6] = fmaf(wi, x1.z, qi[6]); qi[7] = fmaf(wi, x1.w, qi[7]);
        qj[0] = fmaf(wj, x0.x, qj[0]); qj[1] = fmaf(wj, x0.y, qj[1]);
        qj[2] = fmaf(wj, x0.z, qj[2]); qj[3] = fmaf(wj, x0.w, qj[3]);
        qj[4] = fmaf(wj, x1.x, qj[4]); qj[5] = fmaf(wj, x1.y, qj[5]);
        qj[6] = fmaf(wj, x1.z, qj[6]); qj[7] = fmaf(wj, x1.w, qj[7]);
        af[0] = fmaf(wa, x0.x, af[0]); af[1] = fmaf(wa, x0.y, af[1]);
        af[2] = fmaf(wa, x0.z, af[2]); af[3] = fmaf(wa, x0.w, af[3]);
        af[4] = fmaf(wa, x1.x, af[4]); af[5] = fmaf(wa, x1.y, af[5]);
        af[6] = fmaf(wa, x1.z, af[6]); af[7] = fmaf(wa, x1.w, af[7]);
    }
#pragma unroll
    for (int kk = 0; kk < 8; ++kk) {
        long o = (long)(base + k0 + kk) * 64 + c;
        g_Qi[o] = qi[kk];
        g_Qj[o] = qj[kk];
        g_AF[o] = af[kk];
    }
}

// ---------------- kernel 4: fused per-query (2c-tiles, in-warp softmax) ----------------
struct P2 {
    const float *qxyz, *sxyz;
    const int   *qmask;
    const float *Wth1, *bth1, *Wth2, *bth2;
    const float *bal;
    const float *gt, *bet, *rmt, *rvt, *gg, *beg, *rmg, *rvg;
    float* out;
};

#define KST 68   // [k][c] row stride for Qj/AF staging

constexpr int OFF_WG   = 0;       // WgT[c2][c] 4096
constexpr int OFF_WEFF = 4096;    // 64*4 theta-fold
constexpr int OFF_CC   = 4352;    // bal | bconst
constexpr int OFF_BN   = 4480;    // 4*64
constexpr int OFF_Q    = 4736;
// per-query: dl [64*36] | Qj [32*68] | AF [32*68] | pos [32*4] | fm [32] | qi [64] | kidx [32]
constexpr int QO_DL = 0, QO_QJ = 2304, QO_AF = 4480;
constexpr int QO_POS = 6656, QO_FM = 6784, QO_QI = 6816, QO_KIDX = 6880;
constexpr int QSZ = 6912;
constexpr int SMEM_FLOATS = OFF_Q + 2 * QSZ;   // 18560 floats = 74240 B

__global__ __launch_bounds__(256, 2) void k_main(P2 p) {
    extern __shared__ float sm[];
    int tid = threadIdx.x;

    {
        for (int i = tid; i < 4096; i += 256) {
            int o = i >> 6, in = i & 63;
            sm[OFF_WG + in * 64 + o] = g_Wgeff[i];
        }
        if (tid < 192) {
            int cc = tid / 3, j = tid - 3 * cc;
            float acc = 0.f;
            for (int c2 = 0; c2 < 64; ++c2)
                acc = fmaf(p.Wth2[cc * 64 + c2], p.Wth1[c2 * 3 + j], acc);
            sm[OFF_WEFF + cc * 4 + j] = acc;
        } else {
            int cc = tid - 192;
            float acc = p.bth2[cc];
            for (int c2 = 0; c2 < 64; ++c2)
                acc = fmaf(p.Wth2[cc * 64 + c2], p.bth1[c2], acc);
            sm[OFF_WEFF + cc * 4 + 3] = acc;
        }
        if (tid < 64) {
            int i = tid;
            sm[OFF_CC + i]      = p.bal[i];
            sm[OFF_CC + 64 + i] = g_bconst[i];
            float it = p.gt[i] * rsqrtf(p.rvt[i] + EPSV);
            sm[OFF_BN + 0 * 64 + i] = it;
            sm[OFF_BN + 1 * 64 + i] = p.bet[i] - p.rmt[i] * it;
            float ig = p.gg[i] * rsqrtf(p.rvg[i] + EPSV);
            sm[OFF_BN + 2 * 64 + i] = ig;
            sm[OFF_BN + 3 * 64 + i] = p.beg[i] - p.rmg[i] * ig;
        }
    }
    __syncthreads();

    int q  = tid >> 7;            // query slot 0..1
    int tq = tid & 127;
    int g  = tq & 3;              // k-group (lane bits 0-1!)
    int cp = tq >> 2;             // c-pair 0..31
    int c0 = cp * 2;
    int c1 = c0 + 1;
    int k0 = g * 8;

    float* Q    = sm + OFF_Q + q * QSZ;
    float* dlB  = Q + QO_DL;
    float* QjB  = Q + QO_QJ;
    float* AFB  = Q + QO_AF;
    float* posB = Q + QO_POS;
    float* fmB  = Q + QO_FM;
    float* qiB  = Q + QO_QI;
    int*   kidx = (int*)(Q + QO_KIDX);

    // per-channel constants for both channels
    float b_al0 = sm[OFF_CC + c0],      b_al1 = sm[OFF_CC + c1];
    float bcn0  = sm[OFF_CC + 64 + c0], bcn1  = sm[OFF_CC + 64 + c1];
    float invt0 = sm[OFF_BN + c0],      invt1 = sm[OFF_BN + c1];
    float sht0  = sm[OFF_BN + 64 + c0], sht1  = sm[OFF_BN + 64 + c1];
    float invg0 = sm[OFF_BN + 128 + c0], invg1 = sm[OFF_BN + 128 + c1];
    float shg0  = sm[OFF_BN + 192 + c0], shg1  = sm[OFF_BN + 192 + c1];
    float4 we_0 = *(const float4*)(sm + OFF_WEFF + c0 * 4);
    float4 we_1 = *(const float4*)(sm + OFF_WEFF + c1 * 4);

    const int ngrp = (BB * NN) / 2;
    for (int grp = blockIdx.x; grp < ngrp; grp += gridDim.x) {
        int qi = grp * 2 + q;
        int b  = qi >> 12;
        int n  = qi & (NN - 1);
        long rowbase = (long)b * MM;

        // ---- setup ----
        if (tq < 32) {
            int k  = tq;
            int ki = g_idx[qi * KK + k];
            kidx[k] = ki;
            float qx = p.qxyz[qi * 3 + 0];
            float qy = p.qxyz[qi * 3 + 1];
            float qz = p.qxyz[qi * 3 + 2];
            const float* s = p.sxyz + (rowbase + ki) * 3;
            float4 pp;
            pp.x = (s[0] - qx) * (1.0f / RADIUS);
            pp.y = (s[1] - qy) * (1.0f / RADIUS);
            pp.z = (s[2] - qz) * (1.0f / RADIUS);
            pp.w = 0.f;
            *(float4*)(posB + k * 4) = pp;
            unsigned nb = g_nbr[qi];
            int qm = p.qmask[qi];
            fmB[k] = (float)((nb >> k) & 1u) + (1.0f - (float)qm);
        } else if (tq < 96) {
            int cc = tq - 32;
            qiB[cc] = g_Qi[(rowbase + g_idxnn[qi]) * 64 + cc];
        }
        __syncthreads();   // S1

        // ---- gather Qj/AF as [k][c] rows, float4 ----
#pragma unroll
        for (int step = 0; step < 4; ++step) {
            int i = tq + step * 128;          // 0..511 float4 slots
            int k = i >> 4, c4 = (i & 15) * 4;
            long o = (rowbase + kidx[k]) * 64 + c4;
            *(float4*)(QjB + k * KST + c4) = *(const float4*)(g_Qj + o);
            *(float4*)(AFB + k * KST + c4) = *(const float4*)(g_AF + o);
        }
        // ---- delta for (c0,c1) x own 8 k; keep in regs + store to dlB ----
        float dl0[8], dl1[8];
        {
            float4 a0, a1, b0v, b1v;
#pragma unroll
            for (int kk = 0; kk < 8; ++kk) {
                float4 pp = *(const float4*)(posB + (k0 + kk) * 4);
                float d0 = we_0.w, d1 = we_1.w;
                d0 = fmaf(we_0.x, pp.x, d0); d1 = fmaf(we_1.x, pp.x, d1);
                d0 = fmaf(we_0.y, pp.y, d0); d1 = fmaf(we_1.y, pp.y, d1);
                d0 = fmaf(we_0.z, pp.z, d0); d1 = fmaf(we_1.z, pp.z, d1);
                dl0[kk] = fmaxf(fmaf(d0, invt0, sht0), 0.f);
                dl1[kk] = fmaxf(fmaf(d1, invt1, sht1), 0.f);
                if (kk < 4) { (&a0.x)[kk] = dl0[kk]; (&b0v.x)[kk] = dl1[kk]; }
                else        { (&a1.x)[kk - 4] = dl0[kk]; (&b1v.x)[kk - 4] = dl1[kk]; }
            }
            *(float4*)(dlB + c0 * STRD + k0)     = a0;
            *(float4*)(dlB + c0 * STRD + k0 + 4) = a1;
            *(float4*)(dlB + c1 * STRD + k0)     = b0v;
            *(float4*)(dlB + c1 * STRD + k0 + 4) = b1v;
        }
        __syncthreads();   // S2

        // ---- matvec: (Wgeff @ delta) rows c0,c1, k in [k0,k0+8) ----
        float acc0[8], acc1[8];
#pragma unroll
        for (int kk = 0; kk < 8; ++kk) { acc0[kk] = 0.f; acc1[kk] = 0.f; }
        {
            const float* W  = sm + OFF_WG + c0;
            const float* db = dlB + k0;
#pragma unroll 4
            for (int c2 = 0; c2 < 64; ++c2) {
                float2 w2 = *(const float2*)(W + c2 * 64);
                float4 d0 = *(const float4*)(db + c2 * STRD);
                float4 d1 = *(const float4*)(db + c2 * STRD + 4);
                acc0[0] = fmaf(w2.x, d0.x, acc0[0]); acc1[0] = fmaf(w2.y, d0.x, acc1[0]);
                acc0[1] = fmaf(w2.x, d0.y, acc0[1]); acc1[1] = fmaf(w2.y, d0.y, acc1[1]);
                acc0[2] = fmaf(w2.x, d0.z, acc0[2]); acc1[2] = fmaf(w2.y, d0.z, acc1[2]);
                acc0[3] = fmaf(w2.x, d0.w, acc0[3]); acc1[3] = fmaf(w2.y, d0.w, acc1[3]);
                acc0[4] = fmaf(w2.x, d1.x, acc0[4]); acc1[4] = fmaf(w2.y, d1.x, acc1[4]);
                acc0[5] = fmaf(w2.x, d1.y, acc0[5]); acc1[5] = fmaf(w2.y, d1.y, acc1[5]);
                acc0[6] = fmaf(w2.x, d1.z, acc0[6]); acc1[6] = fmaf(w2.y, d1.z, acc1[6]);
                acc0[7] = fmaf(w2.x, d1.w, acc0[7]); acc1[7] = fmaf(w2.y, d1.w, acc1[7]);
            }
        }

        // ---- epilogue: rel2 + ft, in-warp softmax over k ----
        float qic0 = qiB[c0], qic1 = qiB[c1];
        float ft0[8], ft1[8];
#pragma unroll
        for (int kk = 0; kk < 8; ++kk) {
            int k = k0 + kk;
            float2 qj = *(const float2*)(QjB + k * KST + c0);
            float2 af = *(const float2*)(AFB + k * KST + c0);
            float fm  = fmB[k];
            float p0 = qic0 - qj.x + acc0[kk] + bcn0;
            float p1 = qic1 - qj.y + acc1[kk] + bcn1;
            acc0[kk] = fmaxf(fmaf(p0, invg0, shg0), 0.f);
            acc1[kk] = fmaxf(fmaf(p1, invg1, shg1), 0.f);
            ft0[kk] = (af.x + b_al0 + dl0[kk]) * fm;
            ft1[kk] = (af.y + b_al1 + dl1[kk]) * fm;
        }
        float mx0 = acc0[0], mx1 = acc1[0];
#pragma unroll
        for (int kk = 1; kk < 8; ++kk) {
            mx0 = fmaxf(mx0, acc0[kk]);
            mx1 = fmaxf(mx1, acc1[kk]);
        }
        mx0 = fmaxf(mx0, __shfl_xor_sync(0xffffffffu, mx0, 1));
        mx0 = fmaxf(mx0, __shfl_xor_sync(0xffffffffu, mx0, 2));
        mx1 = fmaxf(mx1, __shfl_xor_sync(0xffffffffu, mx1, 1));
        mx1 = fmaxf(mx1, __shfl_xor_sync(0xffffffffu, mx1, 2));

        float se0 = 0.f, sf0 = 0.f, se1 = 0.f, sf1 = 0.f;
#pragma unroll
        for (int kk = 0; kk < 8; ++kk) {
            float e0 = __expf(acc0[kk] - mx0);
            float e1 = __expf(acc1[kk] - mx1);
            se0 += e0; sf0 = fmaf(e0, ft0[kk], sf0);
            se1 += e1; sf1 = fmaf(e1, ft1[kk], sf1);
        }
        se0 += __shfl_xor_sync(0xffffffffu, se0, 1);
        se0 += __shfl_xor_sync(0xffffffffu, se0, 2);
        sf0 += __shfl_xor_sync(0xffffffffu, sf0, 1);
        sf0 += __shfl_xor_sync(0xffffffffu, sf0, 2);
        se1 += __shfl_xor_sync(0xffffffffu, se1, 1);
        se1 += __shfl_xor_sync(0xffffffffu, se1, 2);
        sf1 += __shfl_xor_sync(0xffffffffu, sf1, 1);
        sf1 += __shfl_xor_sync(0xffffffffu, sf1, 2);
        if (g == 0) {
            p.out[((long)b * CCH + c0) * NN + n] = sf0 / se0;
            p.out[((long)b * CCH + c1) * NN + n] = sf1 / se1;
        }
        __syncthreads();   // S3
    }
}

// ---------------- host launcher ----------------
extern "C" void kernel_launch(void* const* d_in, const int* in_sizes, int n_in,
                              void* d_out, int out_size) {
    const float* qxyz  = (const float*)d_in[0];
    const float* sxyz  = (const float*)d_in[1];
    const int*   qmask = (const int*)d_in[2];
    const int*   smask = (const int*)d_in[3];
    const float* feat  = (const float*)d_in[4];
    const float* Wth1  = (const float*)d_in[5];
    const float* bth1  = (const float*)d_in[6];
    const float* Wth2  = (const float*)d_in[7];
    const float* bth2  = (const float*)d_in[8];
    const float* Wphi  = (const float*)d_in[9];
    const float* bphi  = (const float*)d_in[10];
    const float* Wpsi  = (const float*)d_in[11];
    const float* bpsi  = (const float*)d_in[12];
    const float* Wal   = (const float*)d_in[13];
    const float* bal   = (const float*)d_in[14];
    const float* Wg1   = (const float*)d_in[15];
    const float* bg1   = (const float*)d_in[16];
    const float* Wg2   = (const float*)d_in[17];
    const float* bg2   = (const float*)d_in[18];

    P2 p;
    p.qxyz = qxyz; p.sxyz = sxyz; p.qmask = qmask;
    p.Wth1 = Wth1; p.bth1 = bth1; p.Wth2 = Wth2; p.bth2 = bth2;
    p.bal  = bal;
    p.gt   = (const float*)d_in[19]; p.bet  = (const float*)d_in[20];
    p.rmt  = (const float*)d_in[21]; p.rvt  = (const float*)d_in[22];
    p.gg   = (const float*)d_in[23]; p.beg  = (const float*)d_in[24];
    p.rmg  = (const float*)d_in[25]; p.rvg  = (const float*)d_in[26];
    p.out  = (float*)d_out;

    k_compose<<<1, 256>>>(Wg1, Wg2, Wphi, Wpsi, bphi, bpsi, bg1, bg2);

    cudaFuncSetAttribute(k_knn, cudaFuncAttributeMaxDynamicSharedMemorySize,
                         KNN_SM_FLOATS * 4);
    k_knn<<<(BB * NN) / 8, 256, KNN_SM_FLOATS * 4>>>(qxyz, sxyz, smask);

    cudaFuncSetAttribute(k_pre, cudaFuncAttributeMaxDynamicSharedMemorySize,
                         PRE_SM * 4);
    k_pre<<<(BB * MM) / 32, 256, PRE_SM * 4>>>(feat, Wal);

    cudaFuncSetAttribute(k_main, cudaFuncAttributeMaxDynamicSharedMemorySize,
                         SMEM_FLOATS * 4);
    int dev = 0, nsm = 148;
    cudaGetDevice(&dev);
    cudaDeviceGetAttribute(&nsm, cudaDevAttrMultiProcessorCount, dev);
    k_main<<<2 * nsm, 256, SMEM_FLOATS * 4>>>(p);
}

// round 8
// speedup vs baseline: 2.7681x; 1.0561x over previous
#include <cuda_runtime.h>
#include <math.h>

#define BB 4
#define NN 4096
#define MM 4096
#define CCH 64
#define KK 32
#define RADIUS 0.1f
#define RAD2 0.01f
#define EPSV 1e-5f

// ---------------- device scratch ----------------
__device__ int      g_idx[BB * NN * KK];
__device__ unsigned g_nbr[BB * NN];
__device__ int      g_idxnn[BB * NN];
__device__ float    g_Wgeff[CCH * CCH];
__device__ float    g_Wqi[CCH * CCH];
__device__ float    g_Wqj[CCH * CCH];
__device__ float    g_bconst[CCH];
__device__ float    g_Qi[BB * MM * CCH];
__device__ float    g_Qj[BB * MM * CCH];
__device__ float    g_AF[BB * MM * CCH];

// ---------------- warp-bitonic helpers ----------------
__device__ __forceinline__ void bsort32(float& d, int& ix, int lane) {
#pragma unroll
    for (int k = 2; k <= 32; k <<= 1) {
#pragma unroll
        for (int j = k >> 1; j > 0; j >>= 1) {
            float od = __shfl_xor_sync(0xffffffffu, d, j);
            int   oi = __shfl_xor_sync(0xffffffffu, ix, j);
            bool keepMin = (((lane & k) == 0) == ((lane & j) == 0));
            bool take = keepMin ? (od < d) : (od > d);
            if (take) { d = od; ix = oi; }
        }
    }
}
__device__ __forceinline__ void bmerge32(float& d, int& ix, int lane) {
#pragma unroll
    for (int j = 16; j > 0; j >>= 1) {
        float od = __shfl_xor_sync(0xffffffffu, d, j);
        int   oi = __shfl_xor_sync(0xffffffffu, ix, j);
        bool keepMin = ((lane & j) == 0);
        bool take = keepMin ? (od < d) : (od > d);
        if (take) { d = od; ix = oi; }
    }
}

// ---------------- kernel 1: top-K with candidate buffering ----------------
constexpr int KNN_SM_FLOATS = 3 * MM + 8 * 64 * 2;

__global__ __launch_bounds__(256) void k_knn(const float* __restrict__ qxyz,
                                             const float* __restrict__ sxyz,
                                             const int* __restrict__ smask) {
    extern __shared__ float dsm[];
    float* sx = dsm;
    float* sy = dsm + MM;
    float* sz = dsm + 2 * MM;
    int b   = blockIdx.x >> 9;
    int grp = blockIdx.x & 511;
    for (int i = threadIdx.x; i < MM; i += 256) {
        bool v = smask[b * MM + i] > 0;
        float x = sxyz[(b * MM + i) * 3 + 0];
        float y = sxyz[(b * MM + i) * 3 + 1];
        float z = sxyz[(b * MM + i) * 3 + 2];
        sx[i] = v ? x : 1e18f;
        sy[i] = v ? y : 1e18f;
        sz[i] = v ? z : 1e18f;
    }
    __syncthreads();

    int warp = threadIdx.x >> 5, lane = threadIdx.x & 31;
    float* bD = dsm + 3 * MM + warp * 64;
    int*   bI = (int*)(dsm + 3 * MM + 512) + warp * 64;

    int n  = grp * 8 + warp;
    int qi = b * NN + n;
    float qx = qxyz[qi * 3 + 0];
    float qy = qxyz[qi * 3 + 1];
    float qz = qxyz[qi * 3 + 2];

    float bd = INFINITY; int bi = 0;
    float thr = INFINITY;
    int cnt = 0;
    for (int ch = 0; ch < MM / 32; ++ch) {
        int m = ch * 32 + lane;
        float dx = qx - sx[m], dy = qy - sy[m], dz = qz - sz[m];
        float d2 = fmaf(dx, dx, fmaf(dy, dy, dz * dz));
        bool pass = d2 < thr;
        unsigned mask = __ballot_sync(0xffffffffu, pass);
        if (mask) {
            int pos = cnt + __popc(mask & ((1u << lane) - 1u));
            if (pass) { bD[pos] = d2; bI[pos] = m; }
            cnt += __popc(mask);
            if (cnt >= 32) {
                __syncwarp();
                float nd = bD[lane]; int ni = bI[lane];
                bsort32(nd, ni, lane);
                float rd = __shfl_sync(0xffffffffu, nd, 31 ^ lane);
                int   ri = __shfl_sync(0xffffffffu, ni, 31 ^ lane);
                if (rd < bd) { bd = rd; bi = ri; }
                bmerge32(bd, bi, lane);
                thr = __shfl_sync(0xffffffffu, bd, 31);
                cnt -= 32;
                float sd = 0.f; int si = 0;
                if (lane < cnt) { sd = bD[32 + lane]; si = bI[32 + lane]; }
                __syncwarp();
                if (lane < cnt) { bD[lane] = sd; bI[lane] = si; }
                __syncwarp();
            }
        }
    }
    if (cnt > 0) {
        __syncwarp();
        float nd = (lane < cnt) ? bD[lane] : INFINITY;
        int   ni = (lane < cnt) ? bI[lane] : 0;
        bsort32(nd, ni, lane);
        float rd = __shfl_sync(0xffffffffu, nd, 31 ^ lane);
        int   ri = __shfl_sync(0xffffffffu, ni, 31 ^ lane);
        if (rd < bd) { bd = rd; bi = ri; }
        bmerge32(bd, bi, lane);
    }
    g_idx[qi * KK + lane] = bi;
    unsigned nb = __ballot_sync(0xffffffffu, bd <= RAD2);
    if (lane == 0) { g_nbr[qi] = nb; g_idxnn[qi] = bi; }
}

// ---------------- kernel 2: compose weight matrices ----------------
__global__ __launch_bounds__(256) void k_compose(
    const float* __restrict__ Wg1, const float* __restrict__ Wg2,
    const float* __restrict__ Wphi, const float* __restrict__ Wpsi,
    const float* __restrict__ bphi, const float* __restrict__ bpsi,
    const float* __restrict__ bg1, const float* __restrict__ bg2) {
    __shared__ float G[CCH * CCH];
    int tid = threadIdx.x;
    for (int e = tid; e < 4096; e += 256) {
        int o = e >> 6, i = e & 63;
        float a = 0.f;
        for (int c = 0; c < 64; ++c)
            a = fmaf(Wg2[o * 64 + c], Wg1[c * 64 + i], a);
        G[e] = a;
        g_Wgeff[e] = a;
    }
    __syncthreads();
    for (int e = tid; e < 4096; e += 256) {
        int o = e >> 6, i = e & 63;
        float qi = 0.f, qj = 0.f;
        for (int c = 0; c < 64; ++c) {
            float g = G[o * 64 + c];
            qi = fmaf(g, Wphi[c * 64 + i], qi);
            qj = fmaf(g, Wpsi[c * 64 + i], qj);
        }
        g_Wqi[e] = qi;
        g_Wqj[e] = qj;
    }
    if (tid < 64) {
        float a = bg2[tid];
        for (int c = 0; c < 64; ++c)
            a = fmaf(Wg2[tid * 64 + c], bg1[c], a);
        for (int i = 0; i < 64; ++i)
            a = fmaf(G[tid * 64 + i], bphi[i] - bpsi[i], a);
        g_bconst[tid] = a;
    }
}

// ---------------- kernel 3: per-support precompute ----------------
#define STRD 36
constexpr int PRE_WQI = 0, PRE_WQJ = 4096, PRE_WAL = 8192, PRE_X = 12288;
constexpr int PRE_SM = PRE_X + 64 * STRD;

__global__ __launch_bounds__(256) void k_pre(const float* __restrict__ feat,
                                             const float* __restrict__ Wal) {
    extern __shared__ float s[];
    int tid = threadIdx.x;
    for (int e = tid; e < 4096; e += 256) {
        int o = e >> 6, in = e & 63;
        s[PRE_WQI + in * 64 + o] = g_Wqi[e];
        s[PRE_WQJ + in * 64 + o] = g_Wqj[e];
        s[PRE_WAL + in * 64 + o] = Wal[e];
    }

    int base = blockIdx.x * 32;
    int b    = base >> 12;
    int m0   = base & (MM - 1);
    int c = tid & 63, g = tid >> 6, k0 = g * 8;
    float* xS = s + PRE_X;
    for (int i = tid; i < 2048; i += 256) {
        int k = i & 31, cc = i >> 5;
        xS[cc * STRD + k] = feat[((long)b * CCH + cc) * MM + m0 + k];
    }
    __syncthreads();

    float qi[8], qj[8], af[8];
#pragma unroll
    for (int kk = 0; kk < 8; ++kk) { qi[kk] = 0.f; qj[kk] = 0.f; af[kk] = 0.f; }
    const float* Wi = s + PRE_WQI + c;
    const float* Wj = s + PRE_WQJ + c;
    const float* Wa = s + PRE_WAL + c;
    const float* xb = xS + k0;
#pragma unroll 4
    for (int c2 = 0; c2 < 64; ++c2) {
        float wi = Wi[c2 * 64], wj = Wj[c2 * 64], wa = Wa[c2 * 64];
        float4 x0 = *(const float4*)(xb + c2 * STRD);
        float4 x1 = *(const float4*)(xb + c2 * STRD + 4);
        qi[0] = fmaf(wi, x0.x, qi[0]); qi[1] = fmaf(wi, x0.y, qi[1]);
        qi[2] = fmaf(wi, x0.z, qi[2]); qi[3] = fmaf(wi, x0.w, qi[3]);
        qi[4] = fmaf(wi, x1.x, qi[4]); qi[5] = fmaf(wi, x1.y, qi[5]);
        qi[6] = fmaf(wi, x1.z, qi[6]); qi[7] = fmaf(wi, x1.w, qi[7]);
        qj[0] = fmaf(wj, x0.x, qj[0]); qj[1] = fmaf(wj, x0.y, qj[1]);
        qj[2] = fmaf(wj, x0.z, qj[2]); qj[3] = fmaf(wj, x0.w, qj[3]);
        qj[4] = fmaf(wj, x1.x, qj[4]); qj[5] = fmaf(wj, x1.y, qj[5]);
        qj[6] = fmaf(wj, x1.z, qj[6]); qj[7] = fmaf(wj, x1.w, qj[7]);
        af[0] = fmaf(wa, x0.x, af[0]); af[1] = fmaf(wa, x0.y, af[1]);
        af[2] = fmaf(wa, x0.z, af[2]); af[3] = fmaf(wa, x0.w, af[3]);
        af[4] = fmaf(wa, x1.x, af[4]); af[5] = fmaf(wa, x1.y, af[5]);
        af[6] = fmaf(wa, x1.z, af[6]); af[7] = fmaf(wa, x1.w, af[7]);
    }
#pragma unroll
    for (int kk = 0; kk < 8; ++kk) {
        long o = (long)(base + k0 + kk) * 64 + c;
        g_Qi[o] = qi[kk];
        g_Qj[o] = qj[kk];
        g_AF[o] = af[kk];
    }
}

// ---------------- kernel 4: fused per-query (4c x 4k, direct-LDG epilogue) --------
struct P2 {
    const float *qxyz, *sxyz;
    const int   *qmask;
    const float *Wth1, *bth1, *Wth2, *bth2;
    const float *bal;
    const float *gt, *bet, *rmt, *rvt, *gg, *beg, *rmg, *rvg;
    float* out;
};

constexpr int OFF_WG   = 0;       // WgT[c2][c] 4096
constexpr int OFF_WEFF = 4096;    // 64*4 theta-fold
constexpr int OFF_CC   = 4352;    // bal(64) | bconst(64)
constexpr int OFF_BN   = 4480;    // 4*64
constexpr int OFF_Q    = 4736;
// per-query: dl [64*36] | pos [32*4] | fm [32] | kidx [32]
constexpr int QO_DL = 0, QO_POS = 2304, QO_FM = 2432, QO_KIDX = 2464;
constexpr int QSZ = 2496;
constexpr int SMEM_FLOATS = OFF_Q + 2 * QSZ;   // 9728 floats = 38912 B

__global__ __launch_bounds__(256, 2) void k_main(P2 p) {
    extern __shared__ float sm[];
    int tid = threadIdx.x;

    {
        for (int i = tid; i < 4096; i += 256) {
            int o = i >> 6, in = i & 63;
            sm[OFF_WG + in * 64 + o] = g_Wgeff[i];
        }
        if (tid < 192) {
            int cc = tid / 3, j = tid - 3 * cc;
            float acc = 0.f;
            for (int c2 = 0; c2 < 64; ++c2)
                acc = fmaf(p.Wth2[cc * 64 + c2], p.Wth1[c2 * 3 + j], acc);
            sm[OFF_WEFF + cc * 4 + j] = acc;
        } else {
            int cc = tid - 192;
            float acc = p.bth2[cc];
            for (int c2 = 0; c2 < 64; ++c2)
                acc = fmaf(p.Wth2[cc * 64 + c2], p.bth1[c2], acc);
            sm[OFF_WEFF + cc * 4 + 3] = acc;
        }
        if (tid < 64) {
            int i = tid;
            sm[OFF_CC + i]      = p.bal[i];
            sm[OFF_CC + 64 + i] = g_bconst[i];
            float it = p.gt[i] * rsqrtf(p.rvt[i] + EPSV);
            sm[OFF_BN + 0 * 64 + i] = it;
            sm[OFF_BN + 1 * 64 + i] = p.bet[i] - p.rmt[i] * it;
            float ig = p.gg[i] * rsqrtf(p.rvg[i] + EPSV);
            sm[OFF_BN + 2 * 64 + i] = ig;
            sm[OFF_BN + 3 * 64 + i] = p.beg[i] - p.rmg[i] * ig;
        }
    }
    __syncthreads();

    int q  = tid >> 7;            // query slot 0..1
    int tq = tid & 127;
    int g  = tq & 7;              // k-group (lane bits 0-2)
    int cp = tq >> 3;             // channel quad 0..15
    int c0 = cp * 4;
    int k0 = g * 4;

    float* Q    = sm + OFF_Q + q * QSZ;
    float* dlB  = Q + QO_DL;
    float* posB = Q + QO_POS;
    float* fmB  = Q + QO_FM;
    int*   kidx = (int*)(Q + QO_KIDX);

    // loop-invariant channel constants (float4-contiguous at c0)
    float4 bal4  = *(const float4*)(sm + OFF_CC + c0);
    float4 bcn4  = *(const float4*)(sm + OFF_CC + 64 + c0);
    float4 invt4 = *(const float4*)(sm + OFF_BN + 0 * 64 + c0);
    float4 sht4  = *(const float4*)(sm + OFF_BN + 1 * 64 + c0);
    float4 invg4 = *(const float4*)(sm + OFF_BN + 2 * 64 + c0);
    float4 shg4  = *(const float4*)(sm + OFF_BN + 3 * 64 + c0);
    float4 we[4];
#pragma unroll
    for (int j = 0; j < 4; ++j)
        we[j] = *(const float4*)(sm + OFF_WEFF + (c0 + j) * 4);

    const int ngrp = (BB * NN) / 2;
    for (int grp = blockIdx.x; grp < ngrp; grp += gridDim.x) {
        int qi = grp * 2 + q;
        int b  = qi >> 12;
        int n  = qi & (NN - 1);
        long rowbase = (long)b * MM;

        // ---- setup ----
        if (tq < 32) {
            int k  = tq;
            int ki = g_idx[qi * KK + k];
            kidx[k] = ki;
            float qx = p.qxyz[qi * 3 + 0];
            float qy = p.qxyz[qi * 3 + 1];
            float qz = p.qxyz[qi * 3 + 2];
            const float* s = p.sxyz + (rowbase + ki) * 3;
            float4 pp;
            pp.x = (s[0] - qx) * (1.0f / RADIUS);
            pp.y = (s[1] - qy) * (1.0f / RADIUS);
            pp.z = (s[2] - qz) * (1.0f / RADIUS);
            pp.w = 0.f;
            *(float4*)(posB + k * 4) = pp;
            unsigned nb = g_nbr[qi];
            int qm = p.qmask[qi];
            fmB[k] = (float)((nb >> k) & 1u) + (1.0f - (float)qm);
        }
        __syncthreads();   // S1

        // ---- delta for (c0..c0+3) x (k0..k0+3) ----
        {
            float4 row[4];   // row[j] = dl over 4 k for channel c0+j
#pragma unroll
            for (int kk = 0; kk < 4; ++kk) {
                float4 pp = *(const float4*)(posB + (k0 + kk) * 4);
#pragma unroll
                for (int j = 0; j < 4; ++j) {
                    float d = we[j].w;
                    d = fmaf(we[j].x, pp.x, d);
                    d = fmaf(we[j].y, pp.y, d);
                    d = fmaf(we[j].z, pp.z, d);
                    float dl = fmaxf(fmaf(d, (&invt4.x)[j], (&sht4.x)[j]), 0.f);
                    (&row[j].x)[kk] = dl;
                }
            }
#pragma unroll
            for (int j = 0; j < 4; ++j)
                *(float4*)(dlB + (c0 + j) * STRD + k0) = row[j];
        }
        __syncthreads();   // S2

        // ---- matvec: acc[j][kk] = (Wgeff @ delta)[c0+j][k0+kk] ----
        float acc[16];
#pragma unroll
        for (int i = 0; i < 16; ++i) acc[i] = 0.f;
        {
            const float* W  = sm + OFF_WG + c0;
            const float* db = dlB + k0;
#pragma unroll 4
            for (int c2 = 0; c2 < 64; ++c2) {
                float4 w4 = *(const float4*)(W + c2 * 64);
                float4 d4 = *(const float4*)(db + c2 * STRD);
                acc[0]  = fmaf(w4.x, d4.x, acc[0]);
                acc[1]  = fmaf(w4.x, d4.y, acc[1]);
                acc[2]  = fmaf(w4.x, d4.z, acc[2]);
                acc[3]  = fmaf(w4.x, d4.w, acc[3]);
                acc[4]  = fmaf(w4.y, d4.x, acc[4]);
                acc[5]  = fmaf(w4.y, d4.y, acc[5]);
                acc[6]  = fmaf(w4.y, d4.z, acc[6]);
                acc[7]  = fmaf(w4.y, d4.w, acc[7]);
                acc[8]  = fmaf(w4.z, d4.x, acc[8]);
                acc[9]  = fmaf(w4.z, d4.y, acc[9]);
                acc[10] = fmaf(w4.z, d4.z, acc[10]);
                acc[11] = fmaf(w4.z, d4.w, acc[11]);
                acc[12] = fmaf(w4.w, d4.x, acc[12]);
                acc[13] = fmaf(w4.w, d4.y, acc[13]);
                acc[14] = fmaf(w4.w, d4.z, acc[14]);
                acc[15] = fmaf(w4.w, d4.w, acc[15]);
            }
        }

        // ---- epilogue: rel2 -> e (in place), ft, pairwise reductions ----
        int nn = g_idxnn[qi];
        float4 qi4 = *(const float4*)(g_Qi + (rowbase + nn) * 64 + c0);
        float4 dlr[4];
#pragma unroll
        for (int j = 0; j < 4; ++j)
            dlr[j] = *(const float4*)(dlB + (c0 + j) * STRD + k0);

        float ft[16];
#pragma unroll
        for (int kk = 0; kk < 4; ++kk) {
            int k = k0 + kk;
            int row = kidx[k];
            float4 qj4 = *(const float4*)(g_Qj + (rowbase + row) * 64 + c0);
            float4 af4 = *(const float4*)(g_AF + (rowbase + row) * 64 + c0);
            float fm = fmB[k];
#pragma unroll
            for (int j = 0; j < 4; ++j) {
                float pre2 = (&qi4.x)[j] - (&qj4.x)[j] + acc[j * 4 + kk] + (&bcn4.x)[j];
                float v = fmaxf(fmaf(pre2, (&invg4.x)[j], (&shg4.x)[j]), 0.f);
                acc[j * 4 + kk] = __expf(v);     // e  (v >= 0, small: no max needed)
                ft[j * 4 + kk] = ((&af4.x)[j] + (&bal4.x)[j] + (&dlr[j].x)[kk]) * fm;
            }
        }
#pragma unroll
        for (int j = 0; j < 4; ++j) {
            float se = acc[j * 4] + acc[j * 4 + 1] + acc[j * 4 + 2] + acc[j * 4 + 3];
            float sf = acc[j * 4] * ft[j * 4];
            sf = fmaf(acc[j * 4 + 1], ft[j * 4 + 1], sf);
            sf = fmaf(acc[j * 4 + 2], ft[j * 4 + 2], sf);
            sf = fmaf(acc[j * 4 + 3], ft[j * 4 + 3], sf);
            se += __shfl_xor_sync(0xffffffffu, se, 1);
            sf += __shfl_xor_sync(0xffffffffu, sf, 1);
            se += __shfl_xor_sync(0xffffffffu, se, 2);
            sf += __shfl_xor_sync(0xffffffffu, sf, 2);
            se += __shfl_xor_sync(0xffffffffu, se, 4);
            sf += __shfl_xor_sync(0xffffffffu, sf, 4);
            if (g == 0)
                p.out[((long)b * CCH + c0 + j) * NN + n] = sf / se;
        }
        __syncthreads();   // S3
    }
}

// ---------------- host launcher ----------------
extern "C" void kernel_launch(void* const* d_in, const int* in_sizes, int n_in,
                              void* d_out, int out_size) {
    const float* qxyz  = (const float*)d_in[0];
    const float* sxyz  = (const float*)d_in[1];
    const int*   qmask = (const int*)d_in[2];
    const int*   smask = (const int*)d_in[3];
    const float* feat  = (const float*)d_in[4];
    const float* Wth1  = (const float*)d_in[5];
    const float* bth1  = (const float*)d_in[6];
    const float* Wth2  = (const float*)d_in[7];
    const float* bth2  = (const float*)d_in[8];
    const float* Wphi  = (const float*)d_in[9];
    const float* bphi  = (const float*)d_in[10];
    const float* Wpsi  = (const float*)d_in[11];
    const float* bpsi  = (const float*)d_in[12];
    const float* Wal   = (const float*)d_in[13];
    const float* bal   = (const float*)d_in[14];
    const float* Wg1   = (const float*)d_in[15];
    const float* bg1   = (const float*)d_in[16];
    const float* Wg2   = (const float*)d_in[17];
    const float* bg2   = (const float*)d_in[18];

    P2 p;
    p.qxyz = qxyz; p.sxyz = sxyz; p.qmask = qmask;
    p.Wth1 = Wth1; p.bth1 = bth1; p.Wth2 = Wth2; p.bth2 = bth2;
    p.bal  = bal;
    p.gt   = (const float*)d_in[19]; p.bet  = (const float*)d_in[20];
    p.rmt  = (const float*)d_in[21]; p.rvt  = (const float*)d_in[22];
    p.gg   = (const float*)d_in[23]; p.beg  = (const float*)d_in[24];
    p.rmg  = (const float*)d_in[25]; p.rvg  = (const float*)d_in[26];
    p.out  = (float*)d_out;

    k_compose<<<1, 256>>>(Wg1, Wg2, Wphi, Wpsi, bphi, bpsi, bg1, bg2);

    cudaFuncSetAttribute(k_knn, cudaFuncAttributeMaxDynamicSharedMemorySize,
                         KNN_SM_FLOATS * 4);
    k_knn<<<(BB * NN) / 8, 256, KNN_SM_FLOATS * 4>>>(qxyz, sxyz, smask);

    cudaFuncSetAttribute(k_pre, cudaFuncAttributeMaxDynamicSharedMemorySize,
                         PRE_SM * 4);
    k_pre<<<(BB * MM) / 32, 256, PRE_SM * 4>>>(feat, Wal);

    cudaFuncSetAttribute(k_main, cudaFuncAttributeMaxDynamicSharedMemorySize,
                         SMEM_FLOATS * 4);
    int dev = 0, nsm = 148;
    cudaGetDevice(&dev);
    cudaDeviceGetAttribute(&nsm, cudaDevAttrMultiProcessorCount, dev);
    k_main<<<2 * nsm, 256, SMEM_FLOATS * 4>>>(p);
}

// round 9
// speedup vs baseline: 2.7744x; 1.0023x over previous
#include <cuda_runtime.h>
#include <math.h>

#define BB 4
#define NN 4096
#define MM 4096
#define CCH 64
#define KK 32
#define RADIUS 0.1f
#define RAD2 0.01f
#define EPSV 1e-5f

// ---------------- device scratch ----------------
__device__ int      g_idx[BB * NN * KK];
__device__ unsigned g_nbr[BB * NN];
__device__ int      g_idxnn[BB * NN];
__device__ float    g_Wgeff[CCH * CCH];
__device__ float    g_Wqi[CCH * CCH];
__device__ float    g_Wqj[CCH * CCH];
__device__ float    g_bconst[CCH];
__device__ float    g_Qi[BB * MM * CCH];
__device__ float    g_Qj[BB * MM * CCH];
__device__ float    g_AF[BB * MM * CCH];

// ---------------- warp-bitonic helpers ----------------
__device__ __forceinline__ void bsort32(float& d, int& ix, int lane) {
#pragma unroll
    for (int k = 2; k <= 32; k <<= 1) {
#pragma unroll
        for (int j = k >> 1; j > 0; j >>= 1) {
            float od = __shfl_xor_sync(0xffffffffu, d, j);
            int   oi = __shfl_xor_sync(0xffffffffu, ix, j);
            bool keepMin = (((lane & k) == 0) == ((lane & j) == 0));
            bool take = keepMin ? (od < d) : (od > d);
            if (take) { d = od; ix = oi; }
        }
    }
}
__device__ __forceinline__ void bmerge32(float& d, int& ix, int lane) {
#pragma unroll
    for (int j = 16; j > 0; j >>= 1) {
        float od = __shfl_xor_sync(0xffffffffu, d, j);
        int   oi = __shfl_xor_sync(0xffffffffu, ix, j);
        bool keepMin = ((lane & j) == 0);
        bool take = keepMin ? (od < d) : (od > d);
        if (take) { d = od; ix = oi; }
    }
}

// ---------------- kernel 1: top-K with candidate buffering ----------------
constexpr int KNN_SM_FLOATS = 3 * MM + 8 * 64 * 2;

__global__ __launch_bounds__(256) void k_knn(const float* __restrict__ qxyz,
                                             const float* __restrict__ sxyz,
                                             const int* __restrict__ smask) {
    extern __shared__ float dsm[];
    float* sx = dsm;
    float* sy = dsm + MM;
    float* sz = dsm + 2 * MM;
    int b   = blockIdx.x >> 9;
    int grp = blockIdx.x & 511;
    for (int i = threadIdx.x; i < MM; i += 256) {
        bool v = smask[b * MM + i] > 0;
        float x = sxyz[(b * MM + i) * 3 + 0];
        float y = sxyz[(b * MM + i) * 3 + 1];
        float z = sxyz[(b * MM + i) * 3 + 2];
        sx[i] = v ? x : 1e18f;
        sy[i] = v ? y : 1e18f;
        sz[i] = v ? z : 1e18f;
    }
    __syncthreads();

    int warp = threadIdx.x >> 5, lane = threadIdx.x & 31;
    float* bD = dsm + 3 * MM + warp * 64;
    int*   bI = (int*)(dsm + 3 * MM + 512) + warp * 64;

    int n  = grp * 8 + warp;
    int qi = b * NN + n;
    float qx = qxyz[qi * 3 + 0];
    float qy = qxyz[qi * 3 + 1];
    float qz = qxyz[qi * 3 + 2];

    float bd = INFINITY; int bi = 0;
    float thr = INFINITY;
    int cnt = 0;
    for (int ch = 0; ch < MM / 32; ++ch) {
        int m = ch * 32 + lane;
        float dx = qx - sx[m], dy = qy - sy[m], dz = qz - sz[m];
        float d2 = fmaf(dx, dx, fmaf(dy, dy, dz * dz));
        bool pass = d2 < thr;
        unsigned mask = __ballot_sync(0xffffffffu, pass);
        if (mask) {
            int pos = cnt + __popc(mask & ((1u << lane) - 1u));
            if (pass) { bD[pos] = d2; bI[pos] = m; }
            cnt += __popc(mask);
            if (cnt >= 32) {
                __syncwarp();
                float nd = bD[lane]; int ni = bI[lane];
                bsort32(nd, ni, lane);
                float rd = __shfl_sync(0xffffffffu, nd, 31 ^ lane);
                int   ri = __shfl_sync(0xffffffffu, ni, 31 ^ lane);
                if (rd < bd) { bd = rd; bi = ri; }
                bmerge32(bd, bi, lane);
                thr = __shfl_sync(0xffffffffu, bd, 31);
                cnt -= 32;
                float sd = 0.f; int si = 0;
                if (lane < cnt) { sd = bD[32 + lane]; si = bI[32 + lane]; }
                __syncwarp();
                if (lane < cnt) { bD[lane] = sd; bI[lane] = si; }
                __syncwarp();
            }
        }
    }
    if (cnt > 0) {
        __syncwarp();
        float nd = (lane < cnt) ? bD[lane] : INFINITY;
        int   ni = (lane < cnt) ? bI[lane] : 0;
        bsort32(nd, ni, lane);
        float rd = __shfl_sync(0xffffffffu, nd, 31 ^ lane);
        int   ri = __shfl_sync(0xffffffffu, ni, 31 ^ lane);
        if (rd < bd) { bd = rd; bi = ri; }
        bmerge32(bd, bi, lane);
    }
    g_idx[qi * KK + lane] = bi;
    unsigned nb = __ballot_sync(0xffffffffu, bd <= RAD2);
    if (lane == 0) { g_nbr[qi] = nb; g_idxnn[qi] = bi; }
}

// ---------------- kernel 2: compose weight matrices ----------------
__global__ __launch_bounds__(256) void k_compose(
    const float* __restrict__ Wg1, const float* __restrict__ Wg2,
    const float* __restrict__ Wphi, const float* __restrict__ Wpsi,
    const float* __restrict__ bphi, const float* __restrict__ bpsi,
    const float* __restrict__ bg1, const float* __restrict__ bg2) {
    __shared__ float G[CCH * CCH];
    int tid = threadIdx.x;
    for (int e = tid; e < 4096; e += 256) {
        int o = e >> 6, i = e & 63;
        float a = 0.f;
        for (int c = 0; c < 64; ++c)
            a = fmaf(Wg2[o * 64 + c], Wg1[c * 64 + i], a);
        G[e] = a;
        g_Wgeff[e] = a;
    }
    __syncthreads();
    for (int e = tid; e < 4096; e += 256) {
        int o = e >> 6, i = e & 63;
        float qi = 0.f, qj = 0.f;
        for (int c = 0; c < 64; ++c) {
            float g = G[o * 64 + c];
            qi = fmaf(g, Wphi[c * 64 + i], qi);
            qj = fmaf(g, Wpsi[c * 64 + i], qj);
        }
        g_Wqi[e] = qi;
        g_Wqj[e] = qj;
    }
    if (tid < 64) {
        float a = bg2[tid];
        for (int c = 0; c < 64; ++c)
            a = fmaf(Wg2[tid * 64 + c], bg1[c], a);
        for (int i = 0; i < 64; ++i)
            a = fmaf(G[tid * 64 + i], bphi[i] - bpsi[i], a);
        g_bconst[tid] = a;
    }
}

// ---------------- kernel 3: per-support precompute ----------------
#define STRD 36
constexpr int PRE_WQI = 0, PRE_WQJ = 4096, PRE_WAL = 8192, PRE_X = 12288;
constexpr int PRE_SM = PRE_X + 64 * STRD;

__global__ __launch_bounds__(256) void k_pre(const float* __restrict__ feat,
                                             const float* __restrict__ Wal) {
    extern __shared__ float s[];
    int tid = threadIdx.x;
    for (int e = tid; e < 4096; e += 256) {
        int o = e >> 6, in = e & 63;
        s[PRE_WQI + in * 64 + o] = g_Wqi[e];
        s[PRE_WQJ + in * 64 + o] = g_Wqj[e];
        s[PRE_WAL + in * 64 + o] = Wal[e];
    }

    int base = blockIdx.x * 32;
    int b    = base >> 12;
    int m0   = base & (MM - 1);
    int c = tid & 63, g = tid >> 6, k0 = g * 8;
    float* xS = s + PRE_X;
    for (int i = tid; i < 2048; i += 256) {
        int k = i & 31, cc = i >> 5;
        xS[cc * STRD + k] = feat[((long)b * CCH + cc) * MM + m0 + k];
    }
    __syncthreads();

    float qi[8], qj[8], af[8];
#pragma unroll
    for (int kk = 0; kk < 8; ++kk) { qi[kk] = 0.f; qj[kk] = 0.f; af[kk] = 0.f; }
    const float* Wi = s + PRE_WQI + c;
    const float* Wj = s + PRE_WQJ + c;
    const float* Wa = s + PRE_WAL + c;
    const float* xb = xS + k0;
#pragma unroll 4
    for (int c2 = 0; c2 < 64; ++c2) {
        float wi = Wi[c2 * 64], wj = Wj[c2 * 64], wa = Wa[c2 * 64];
        float4 x0 = *(const float4*)(xb + c2 * STRD);
        float4 x1 = *(const float4*)(xb + c2 * STRD + 4);
        qi[0] = fmaf(wi, x0.x, qi[0]); qi[1] = fmaf(wi, x0.y, qi[1]);
        qi[2] = fmaf(wi, x0.z, qi[2]); qi[3] = fmaf(wi, x0.w, qi[3]);
        qi[4] = fmaf(wi, x1.x, qi[4]); qi[5] = fmaf(wi, x1.y, qi[5]);
        qi[6] = fmaf(wi, x1.z, qi[6]); qi[7] = fmaf(wi, x1.w, qi[7]);
        qj[0] = fmaf(wj, x0.x, qj[0]); qj[1] = fmaf(wj, x0.y, qj[1]);
        qj[2] = fmaf(wj, x0.z, qj[2]); qj[3] = fmaf(wj, x0.w, qj[3]);
        qj[4] = fmaf(wj, x1.x, qj[4]); qj[5] = fmaf(wj, x1.y, qj[5]);
        qj[6] = fmaf(wj, x1.z, qj[6]); qj[7] = fmaf(wj, x1.w, qj[7]);
        af[0] = fmaf(wa, x0.x, af[0]); af[1] = fmaf(wa, x0.y, af[1]);
        af[2] = fmaf(wa, x0.z, af[2]); af[3] = fmaf(wa, x0.w, af[3]);
        af[4] = fmaf(wa, x1.x, af[4]); af[5] = fmaf(wa, x1.y, af[5]);
        af[6] = fmaf(wa, x1.z, af[6]); af[7] = fmaf(wa, x1.w, af[7]);
    }
#pragma unroll
    for (int kk = 0; kk < 8; ++kk) {
        long o = (long)(base + k0 + kk) * 64 + c;
        g_Qi[o] = qi[kk];
        g_Qj[o] = qj[kk];
        g_AF[o] = af[kk];
    }
}

// ---------------- kernel 4: fused per-query (4c x 4k, low-reg, 3 CTA/SM) --------
struct P2 {
    const float *qxyz, *sxyz;
    const int   *qmask;
    const float *Wth1, *bth1, *Wth2, *bth2;
    const float *bal;
    const float *gt, *bet, *rmt, *rvt, *gg, *beg, *rmg, *rvg;
    float* out;
};

constexpr int OFF_WG   = 0;       // WgT[c2][c] 4096
constexpr int OFF_WEFF = 4096;    // 64*4 theta-fold
constexpr int OFF_CC   = 4352;    // bal(64) | bconst(64)
constexpr int OFF_BN   = 4480;    // 4*64
constexpr int OFF_Q    = 4736;
// per-query: dl [64*36] | pos [32*4] | fm [32] | kidx [32]
constexpr int QO_DL = 0, QO_POS = 2304, QO_FM = 2432, QO_KIDX = 2464;
constexpr int QSZ = 2496;
constexpr int SMEM_FLOATS = OFF_Q + 2 * QSZ;   // 9728 floats = 38912 B

__global__ __launch_bounds__(256, 3) void k_main(P2 p) {
    extern __shared__ float sm[];
    int tid = threadIdx.x;

    {
        for (int i = tid; i < 4096; i += 256) {
            int o = i >> 6, in = i & 63;
            sm[OFF_WG + in * 64 + o] = g_Wgeff[i];
        }
        if (tid < 192) {
            int cc = tid / 3, j = tid - 3 * cc;
            float acc = 0.f;
            for (int c2 = 0; c2 < 64; ++c2)
                acc = fmaf(p.Wth2[cc * 64 + c2], p.Wth1[c2 * 3 + j], acc);
            sm[OFF_WEFF + cc * 4 + j] = acc;
        } else {
            int cc = tid - 192;
            float acc = p.bth2[cc];
            for (int c2 = 0; c2 < 64; ++c2)
                acc = fmaf(p.Wth2[cc * 64 + c2], p.bth1[c2], acc);
            sm[OFF_WEFF + cc * 4 + 3] = acc;
        }
        if (tid < 64) {
            int i = tid;
            sm[OFF_CC + i]      = p.bal[i];
            sm[OFF_CC + 64 + i] = g_bconst[i];
            float it = p.gt[i] * rsqrtf(p.rvt[i] + EPSV);
            sm[OFF_BN + 0 * 64 + i] = it;
            sm[OFF_BN + 1 * 64 + i] = p.bet[i] - p.rmt[i] * it;
            float ig = p.gg[i] * rsqrtf(p.rvg[i] + EPSV);
            sm[OFF_BN + 2 * 64 + i] = ig;
            sm[OFF_BN + 3 * 64 + i] = p.beg[i] - p.rmg[i] * ig;
        }
    }
    __syncthreads();

    int q  = tid >> 7;            // query slot 0..1
    int tq = tid & 127;
    int g  = tq & 7;              // k-group (lane bits 0-2)
    int cp = tq >> 3;             // channel quad 0..15
    int c0 = cp * 4;
    int k0 = g * 4;

    float* Q    = sm + OFF_Q + q * QSZ;
    float* dlB  = Q + QO_DL;
    float* posB = Q + QO_POS;
    float* fmB  = Q + QO_FM;
    int*   kidx = (int*)(Q + QO_KIDX);

    const int ngrp = (BB * NN) / 2;
    for (int grp = blockIdx.x; grp < ngrp; grp += gridDim.x) {
        int qi = grp * 2 + q;
        int b  = qi >> 12;
        int n  = qi & (NN - 1);
        long rowbase = (long)b * MM;

        // ---- setup ----
        if (tq < 32) {
            int k  = tq;
            int ki = g_idx[qi * KK + k];
            kidx[k] = ki;
            float qx = p.qxyz[qi * 3 + 0];
            float qy = p.qxyz[qi * 3 + 1];
            float qz = p.qxyz[qi * 3 + 2];
            const float* s = p.sxyz + (rowbase + ki) * 3;
            float4 pp;
            pp.x = (s[0] - qx) * (1.0f / RADIUS);
            pp.y = (s[1] - qy) * (1.0f / RADIUS);
            pp.z = (s[2] - qz) * (1.0f / RADIUS);
            pp.w = 0.f;
            *(float4*)(posB + k * 4) = pp;
            unsigned nb = g_nbr[qi];
            int qm = p.qmask[qi];
            fmB[k] = (float)((nb >> k) & 1u) + (1.0f - (float)qm);
        }
        __syncthreads();   // S1

        // ---- delta for (c0..c0+3) x (k0..k0+3): row[j] kept live ----
        float4 row[4];
        {
            float4 invt4 = *(const float4*)(sm + OFF_BN + 0 * 64 + c0);
            float4 sht4  = *(const float4*)(sm + OFF_BN + 1 * 64 + c0);
#pragma unroll
            for (int kk = 0; kk < 4; ++kk) {
                float4 pp = *(const float4*)(posB + (k0 + kk) * 4);
#pragma unroll
                for (int j = 0; j < 4; ++j) {
                    float4 wej = *(const float4*)(sm + OFF_WEFF + (c0 + j) * 4);
                    float d = wej.w;
                    d = fmaf(wej.x, pp.x, d);
                    d = fmaf(wej.y, pp.y, d);
                    d = fmaf(wej.z, pp.z, d);
                    (&row[j].x)[kk] = fmaxf(fmaf(d, (&invt4.x)[j], (&sht4.x)[j]), 0.f);
                }
            }
#pragma unroll
            for (int j = 0; j < 4; ++j)
                *(float4*)(dlB + (c0 + j) * STRD + k0) = row[j];
        }
        __syncthreads();   // S2

        // ---- matvec: acc[j][kk] = (Wgeff @ delta)[c0+j][k0+kk] ----
        float acc[16];
#pragma unroll
        for (int i = 0; i < 16; ++i) acc[i] = 0.f;
        {
            const float* W  = sm + OFF_WG + c0;
            const float* db = dlB + k0;
#pragma unroll 4
            for (int c2 = 0; c2 < 64; ++c2) {
                float4 w4 = *(const float4*)(W + c2 * 64);
                float4 d4 = *(const float4*)(db + c2 * STRD);
                acc[0]  = fmaf(w4.x, d4.x, acc[0]);
                acc[1]  = fmaf(w4.x, d4.y, acc[1]);
                acc[2]  = fmaf(w4.x, d4.z, acc[2]);
                acc[3]  = fmaf(w4.x, d4.w, acc[3]);
                acc[4]  = fmaf(w4.y, d4.x, acc[4]);
                acc[5]  = fmaf(w4.y, d4.y, acc[5]);
                acc[6]  = fmaf(w4.y, d4.z, acc[6]);
                acc[7]  = fmaf(w4.y, d4.w, acc[7]);
                acc[8]  = fmaf(w4.z, d4.x, acc[8]);
                acc[9]  = fmaf(w4.z, d4.y, acc[9]);
                acc[10] = fmaf(w4.z, d4.z, acc[10]);
                acc[11] = fmaf(w4.z, d4.w, acc[11]);
                acc[12] = fmaf(w4.w, d4.x, acc[12]);
                acc[13] = fmaf(w4.w, d4.y, acc[13]);
                acc[14] = fmaf(w4.w, d4.z, acc[14]);
                acc[15] = fmaf(w4.w, d4.w, acc[15]);
            }
        }

        // ---- fused epilogue: rel2 -> e, ft on the fly, se/sf accumulate ----
        float se[4] = {0.f, 0.f, 0.f, 0.f};
        float sf[4] = {0.f, 0.f, 0.f, 0.f};
        {
            int nn = g_idxnn[qi];
            float4 qi4  = *(const float4*)(g_Qi + (rowbase + nn) * 64 + c0);
            float4 bal4 = *(const float4*)(sm + OFF_CC + c0);
            float4 bcn4 = *(const float4*)(sm + OFF_CC + 64 + c0);
            float4 invg4 = *(const float4*)(sm + OFF_BN + 2 * 64 + c0);
            float4 shg4  = *(const float4*)(sm + OFF_BN + 3 * 64 + c0);
#pragma unroll
            for (int kk = 0; kk < 4; ++kk) {
                int k = k0 + kk;
                int ridx = kidx[k];
                float4 qj4 = *(const float4*)(g_Qj + (rowbase + ridx) * 64 + c0);
                float4 af4 = *(const float4*)(g_AF + (rowbase + ridx) * 64 + c0);
                float fm = fmB[k];
#pragma unroll
                for (int j = 0; j < 4; ++j) {
                    float pre2 = (&qi4.x)[j] - (&qj4.x)[j] + acc[j * 4 + kk] + (&bcn4.x)[j];
                    float v = fmaxf(fmaf(pre2, (&invg4.x)[j], (&shg4.x)[j]), 0.f);
                    float e = __expf(v);                      // v >= 0, bounded: no max pass
                    float ftv = ((&af4.x)[j] + (&bal4.x)[j] + (&row[j].x)[kk]) * fm;
                    se[j] += e;
                    sf[j] = fmaf(e, ftv, sf[j]);
                }
            }
        }
#pragma unroll
        for (int j = 0; j < 4; ++j) {
            float s1 = se[j], s2 = sf[j];
            s1 += __shfl_xor_sync(0xffffffffu, s1, 1);
            s2 += __shfl_xor_sync(0xffffffffu, s2, 1);
            s1 += __shfl_xor_sync(0xffffffffu, s1, 2);
            s2 += __shfl_xor_sync(0xffffffffu, s2, 2);
            s1 += __shfl_xor_sync(0xffffffffu, s1, 4);
            s2 += __shfl_xor_sync(0xffffffffu, s2, 4);
            if (g == 0)
                p.out[((long)b * CCH + c0 + j) * NN + n] = s2 / s1;
        }
        __syncthreads();   // S3
    }
}

// ---------------- host launcher ----------------
extern "C" void kernel_launch(void* const* d_in, const int* in_sizes, int n_in,
                              void* d_out, int out_size) {
    const float* qxyz  = (const float*)d_in[0];
    const float* sxyz  = (const float*)d_in[1];
    const int*   qmask = (const int*)d_in[2];
    const int*   smask = (const int*)d_in[3];
    const float* feat  = (const float*)d_in[4];
    const float* Wth1  = (const float*)d_in[5];
    const float* bth1  = (const float*)d_in[6];
    const float* Wth2  = (const float*)d_in[7];
    const float* bth2  = (const float*)d_in[8];
    const float* Wphi  = (const float*)d_in[9];
    const float* bphi  = (const float*)d_in[10];
    const float* Wpsi  = (const float*)d_in[11];
    const float* bpsi  = (const float*)d_in[12];
    const float* Wal   = (const float*)d_in[13];
    const float* bal   = (const float*)d_in[14];
    const float* Wg1   = (const float*)d_in[15];
    const float* bg1   = (const float*)d_in[16];
    const float* Wg2   = (const float*)d_in[17];
    const float* bg2   = (const float*)d_in[18];

    P2 p;
    p.qxyz = qxyz; p.sxyz = sxyz; p.qmask = qmask;
    p.Wth1 = Wth1; p.bth1 = bth1; p.Wth2 = Wth2; p.bth2 = bth2;
    p.bal  = bal;
    p.gt   = (const float*)d_in[19]; p.bet  = (const float*)d_in[20];
    p.rmt  = (const float*)d_in[21]; p.rvt  = (const float*)d_in[22];
    p.gg   = (const float*)d_in[23]; p.beg  = (const float*)d_in[24];
    p.rmg  = (const float*)d_in[25]; p.rvg  = (const float*)d_in[26];
    p.out  = (float*)d_out;

    k_compose<<<1, 256>>>(Wg1, Wg2, Wphi, Wpsi, bphi, bpsi, bg1, bg2);

    cudaFuncSetAttribute(k_knn, cudaFuncAttributeMaxDynamicSharedMemorySize,
                         KNN_SM_FLOATS * 4);
    k_knn<<<(BB * NN) / 8, 256, KNN_SM_FLOATS * 4>>>(qxyz, sxyz, smask);

    cudaFuncSetAttribute(k_pre, cudaFuncAttributeMaxDynamicSharedMemorySize,
                         PRE_SM * 4);
    k_pre<<<(BB * MM) / 32, 256, PRE_SM * 4>>>(feat, Wal);

    cudaFuncSetAttribute(k_main, cudaFuncAttributeMaxDynamicSharedMemorySize,
                         SMEM_FLOATS * 4);
    int dev = 0, nsm = 148;
    cudaGetDevice(&dev);
    cudaDeviceGetAttribute(&nsm, cudaDevAttrMultiProcessorCount, dev);
    k_main<<<3 * nsm, 256, SMEM_FLOATS * 4>>>(p);
}